// round 2
// baseline (speedup 1.0000x reference)
#include <cuda_runtime.h>

#define NNODES 50000
#define NEDGES 640000
#define HID    128
#define CLS    64

#define SCAN_BLK 1024
#define NSCANBLK ((NNODES + SCAN_BLK - 1) / SCAN_BLK)   // 49

typedef unsigned long long u64;

// ---------------- scratch (static __device__, no allocation) ----------------
__device__ float g_bufA[NNODES * HID];
__device__ float g_bufB[NNODES * HID];
__device__ float g_dinv[NNODES];
__device__ int   g_cnt[NNODES];
__device__ int   g_rowptr[NNODES + 1];
__device__ int   g_pos[NNODES];
__device__ int   g_bsum[NSCANBLK];
__device__ int   g_srow[NEDGES];
__device__ float g_sdinv[NEDGES];   // dinv[row] aligned with g_srow

// ---------------- packed f32x2 helpers (sm_103a) ----------------
__device__ __forceinline__ u64 pack2(float lo, float hi) {
    u64 r;
    asm("mov.b64 %0, {%1, %2};" : "=l"(r) : "f"(lo), "f"(hi));
    return r;
}
__device__ __forceinline__ void unpack2(float& lo, float& hi, u64 v) {
    asm("mov.b64 {%0, %1}, %2;" : "=f"(lo), "=f"(hi) : "l"(v));
}
__device__ __forceinline__ void fma2(u64& d, u64 a, u64 b) {
    asm("fma.rn.f32x2 %0, %1, %2, %0;" : "+l"(d) : "l"(a), "l"(b));
}

// ---------------- preprocessing ----------------
__global__ void k_clear_cnt() {
    int i = blockIdx.x * blockDim.x + threadIdx.x;
    if (i < NNODES) g_cnt[i] = 0;
}

__global__ void k_count(const int* __restrict__ col) {
    int e = blockIdx.x * blockDim.x + threadIdx.x;
    if (e < NEDGES) atomicAdd(&g_cnt[col[e]], 1);
}

// phase 1: per-block sum of cnt + dinv computation
__global__ void k_sum_dinv() {
    __shared__ int warp_sums[32];
    const int tid  = threadIdx.x;
    const int lane = tid & 31;
    const int wid  = tid >> 5;
    int i = blockIdx.x * SCAN_BLK + tid;
    int c = (i < NNODES) ? g_cnt[i] : 0;
    if (i < NNODES) g_dinv[i] = rsqrtf((float)c + 1.0f);

    int x = c;
    #pragma unroll
    for (int o = 16; o > 0; o >>= 1) x += __shfl_down_sync(0xffffffffu, x, o);
    if (lane == 0) warp_sums[wid] = x;
    __syncthreads();
    if (wid == 0) {
        int s = warp_sums[lane];
        #pragma unroll
        for (int o = 16; o > 0; o >>= 1) s += __shfl_down_sync(0xffffffffu, s, o);
        if (lane == 0) g_bsum[blockIdx.x] = s;
    }
}

// phase 2: exclusive scan of the 49 block sums (one 64-thread block)
__global__ void k_scan_bsum() {
    __shared__ int ws[2];
    const int tid  = threadIdx.x;   // 64
    const int lane = tid & 31;
    const int w    = tid >> 5;
    int v = (tid < NSCANBLK) ? g_bsum[tid] : 0;
    int x = v;
    #pragma unroll
    for (int o = 1; o < 32; o <<= 1) {
        int y = __shfl_up_sync(0xffffffffu, x, o);
        if (lane >= o) x += y;
    }
    if (lane == 31) ws[w] = x;
    __syncthreads();
    int incl = x + ((w == 1) ? ws[0] : 0);
    if (tid < NSCANBLK) g_bsum[tid] = incl - v;   // exclusive
    if (tid == 0) g_rowptr[NNODES] = NEDGES;
}

// phase 3: per-block scan + offset -> rowptr / pos
__global__ void k_scan_apply() {
    __shared__ int warp_sums[32];
    const int tid  = threadIdx.x;
    const int lane = tid & 31;
    const int wid  = tid >> 5;
    int i = blockIdx.x * SCAN_BLK + tid;
    int v = (i < NNODES) ? g_cnt[i] : 0;

    int x = v;
    #pragma unroll
    for (int o = 1; o < 32; o <<= 1) {
        int y = __shfl_up_sync(0xffffffffu, x, o);
        if (lane >= o) x += y;
    }
    if (lane == 31) warp_sums[wid] = x;
    __syncthreads();
    if (wid == 0) {
        int s = warp_sums[lane];
        #pragma unroll
        for (int o = 1; o < 32; o <<= 1) {
            int y = __shfl_up_sync(0xffffffffu, s, o);
            if (lane >= o) s += y;
        }
        warp_sums[lane] = s;
    }
    __syncthreads();
    int excl = g_bsum[blockIdx.x] + x - v + (wid > 0 ? warp_sums[wid - 1] : 0);
    if (i < NNODES) { g_rowptr[i] = excl; g_pos[i] = excl; }
}

__global__ void k_scatter(const int* __restrict__ row, const int* __restrict__ col) {
    int e = blockIdx.x * blockDim.x + threadIdx.x;
    if (e < NEDGES) {
        int c = col[e];
        int r = row[e];
        int p = atomicAdd(&g_pos[c], 1);
        g_srow[p]  = r;
        g_sdinv[p] = g_dinv[r];
    }
}

// ---------------- SGEMM with packed f32x2 FMAs ----------------
// C[M,BN] = A[M,HID] @ W[HID,BN] (+ bias). BM=128, BK=16, TM=8; 256 threads.
template <int BN, int TN>
__global__ void k_gemm(const float* __restrict__ A,
                       const float* __restrict__ W,
                       const float* __restrict__ bias,   // nullptr -> no bias
                       float* __restrict__ C,
                       int M) {
    constexpr int BM = 128;
    constexpr int BK = 16;
    constexpr int TM = 8;
    __shared__ __align__(16) float As[BK][BM];
    __shared__ __align__(16) float Bs[BK][BN];

    const int tid = threadIdx.x;             // 0..255
    const int tx  = tid & 15;                // col group (TN cols each)
    const int ty  = tid >> 4;                // row group (TM rows each)
    const int rowBase = blockIdx.x * BM;

    u64 acc2[TM][TN / 2];
    #pragma unroll
    for (int i = 0; i < TM; i++)
        #pragma unroll
        for (int j = 0; j < TN / 2; j++) acc2[i][j] = 0ull;

    for (int k0 = 0; k0 < HID; k0 += BK) {
        // --- load A tile (BM x BK), store transposed As[k][m] ---
        #pragma unroll
        for (int i = 0; i < 2; i++) {
            int idx = tid + i * 256;                 // 0..511 float4 id
            int r   = idx >> 2;                      // 0..127
            int c4  = (idx & 3) * 4;                 // 0,4,8,12
            float4 v = make_float4(0.f, 0.f, 0.f, 0.f);
            int gr = rowBase + r;
            if (gr < M)
                v = *reinterpret_cast<const float4*>(A + (size_t)gr * HID + k0 + c4);
            As[c4 + 0][r] = v.x;
            As[c4 + 1][r] = v.y;
            As[c4 + 2][r] = v.z;
            As[c4 + 3][r] = v.w;
        }
        // --- load B tile (BK x BN) ---
        constexpr int B4 = (BK * BN) / 4;            // float4 count
        #pragma unroll
        for (int i = 0; i < B4 / 256; i++) {
            int idx = tid + i * 256;
            int r   = idx / (BN / 4);
            int c4  = (idx % (BN / 4)) * 4;
            float4 v = *reinterpret_cast<const float4*>(W + (size_t)(k0 + r) * BN + c4);
            *reinterpret_cast<float4*>(&Bs[r][c4]) = v;
        }
        __syncthreads();

        #pragma unroll
        for (int k = 0; k < BK; k++) {
            float a[TM];
            #pragma unroll
            for (int ii = 0; ii < TM; ii += 4)
                *reinterpret_cast<float4*>(&a[ii]) =
                    *reinterpret_cast<const float4*>(&As[k][ty * TM + ii]);
            u64 a2[TM];
            #pragma unroll
            for (int i = 0; i < TM; i++) a2[i] = pack2(a[i], a[i]);

            u64 b2[TN / 2];
            #pragma unroll
            for (int jj = 0; jj < TN / 4; jj++) {
                ulonglong2 t = *reinterpret_cast<const ulonglong2*>(&Bs[k][tx * TN + jj * 4]);
                b2[2 * jj]     = t.x;
                b2[2 * jj + 1] = t.y;
            }

            #pragma unroll
            for (int i = 0; i < TM; i++)
                #pragma unroll
                for (int j = 0; j < TN / 2; j++)
                    fma2(acc2[i][j], a2[i], b2[j]);
        }
        __syncthreads();
    }

    float bv[TN];
    #pragma unroll
    for (int j = 0; j < TN; j++) bv[j] = bias ? bias[tx * TN + j] : 0.0f;

    #pragma unroll
    for (int i = 0; i < TM; i++) {
        int gr = rowBase + ty * TM + i;
        if (gr < M) {
            float o[TN];
            #pragma unroll
            for (int j = 0; j < TN / 2; j++) unpack2(o[2 * j], o[2 * j + 1], acc2[i][j]);
            #pragma unroll
            for (int j = 0; j < TN; j += 4) {
                float4 v = make_float4(o[j] + bv[j], o[j + 1] + bv[j + 1],
                                       o[j + 2] + bv[j + 2], o[j + 3] + bv[j + 3]);
                *reinterpret_cast<float4*>(C + (size_t)gr * BN + tx * TN + j) = v;
            }
        }
    }
}

// ---------------- neighbor aggregation (+self loop, +bias, ReLU) ----------------
// one warp per node; lane handles 4 contiguous features (float4)
__global__ void k_agg(const float* __restrict__ h,
                      const float* __restrict__ bias,
                      float* __restrict__ out) {
    int gwarp = (blockIdx.x * blockDim.x + threadIdx.x) >> 5;
    int lane  = threadIdx.x & 31;
    if (gwarp >= NNODES) return;
    const int n = gwarp;

    const float dn = g_dinv[n];
    float4 acc = *reinterpret_cast<const float4*>(h + (size_t)n * HID + lane * 4);
    const float sn = dn * dn;
    acc.x *= sn; acc.y *= sn; acc.z *= sn; acc.w *= sn;

    const int beg = g_rowptr[n];
    const int end = g_rowptr[n + 1];

    int e = beg;
    int   r_next = (e < end) ? g_srow[e]  : 0;
    float d_next = (e < end) ? g_sdinv[e] : 0.0f;
    while (e < end) {
        int   r  = r_next;
        float dr = d_next;
        ++e;
        if (e < end) { r_next = g_srow[e]; d_next = g_sdinv[e]; }
        float w = dr * dn;
        float4 hv = *reinterpret_cast<const float4*>(h + (size_t)r * HID + lane * 4);
        acc.x += hv.x * w;
        acc.y += hv.y * w;
        acc.z += hv.z * w;
        acc.w += hv.w * w;
    }

    float4 b = *reinterpret_cast<const float4*>(bias + lane * 4);
    acc.x = fmaxf(acc.x + b.x, 0.0f);
    acc.y = fmaxf(acc.y + b.y, 0.0f);
    acc.z = fmaxf(acc.z + b.z, 0.0f);
    acc.w = fmaxf(acc.w + b.w, 0.0f);
    *reinterpret_cast<float4*>(out + (size_t)n * HID + lane * 4) = acc;
}

// ---------------- launch ----------------
extern "C" void kernel_launch(void* const* d_in, const int* in_sizes, int n_in,
                              void* d_out, int out_size) {
    const float* x    = (const float*)d_in[0];
    const int*   ei   = (const int*)d_in[1];
    const int*   row  = ei;
    const int*   col  = ei + NEDGES;
    const float* W0   = (const float*)d_in[2];
    const float* b0   = (const float*)d_in[3];
    const float* W1   = (const float*)d_in[4];
    const float* b1   = (const float*)d_in[5];
    const float* W2   = (const float*)d_in[6];
    const float* b2   = (const float*)d_in[7];
    const float* Wlin = (const float*)d_in[8];
    const float* blin = (const float*)d_in[9];
    float* out = (float*)d_out;

    float *bufA, *bufB;
    cudaGetSymbolAddress((void**)&bufA, g_bufA);
    cudaGetSymbolAddress((void**)&bufB, g_bufB);

    // preprocessing (per launch; graph is input-dependent)
    k_clear_cnt<<<(NNODES + 255) / 256, 256>>>();
    k_count<<<(NEDGES + 255) / 256, 256>>>(col);
    k_sum_dinv<<<NSCANBLK, SCAN_BLK>>>();
    k_scan_bsum<<<1, 64>>>();
    k_scan_apply<<<NSCANBLK, SCAN_BLK>>>();
    k_scatter<<<(NEDGES + 255) / 256, 256>>>(row, col);

    const int gemm_blocks = (NNODES + 127) / 128;
    const int agg_blocks  = (NNODES * 32 + 255) / 256;

    // layer 0
    k_gemm<128, 8><<<gemm_blocks, 256>>>(x, W0, nullptr, bufA, NNODES);
    k_agg<<<agg_blocks, 256>>>(bufA, b0, bufB);
    // layer 1
    k_gemm<128, 8><<<gemm_blocks, 256>>>(bufB, W1, nullptr, bufA, NNODES);
    k_agg<<<agg_blocks, 256>>>(bufA, b1, bufB);
    // layer 2
    k_gemm<128, 8><<<gemm_blocks, 256>>>(bufB, W2, nullptr, bufA, NNODES);
    k_agg<<<agg_blocks, 256>>>(bufA, b2, bufB);
    // output head
    k_gemm<64, 4><<<gemm_blocks, 256>>>(bufB, Wlin, blin, out, NNODES);
}

// round 3
// speedup vs baseline: 1.5470x; 1.5470x over previous
#include <cuda_runtime.h>

#define NNODES 50000
#define NEDGES 640000
#define HID    128
#define CLS    64

#define SCAN_BLK 1024
#define NSCANBLK ((NNODES + SCAN_BLK - 1) / SCAN_BLK)   // 49

// ---------------- scratch (static __device__, no allocation) ----------------
__device__ float g_bufA[NNODES * HID];
__device__ float g_bufB[NNODES * HID];
__device__ float g_dinv[NNODES];
__device__ int   g_cnt[NNODES];
__device__ int   g_rowptr[NNODES + 1];
__device__ int   g_pos[NNODES];
__device__ int   g_bsum[NSCANBLK];
__device__ int   g_srow[NEDGES];
__device__ float g_sdinv[NEDGES];   // dinv[row] aligned with g_srow

// ---------------- preprocessing ----------------
__global__ void k_count(const int* __restrict__ col) {
    int e = blockIdx.x * blockDim.x + threadIdx.x;
    if (e < NEDGES) atomicAdd(&g_cnt[col[e]], 1);
}

// phase 1: per-block sum of cnt + dinv computation
__global__ void k_sum_dinv() {
    __shared__ int warp_sums[32];
    const int tid  = threadIdx.x;
    const int lane = tid & 31;
    const int wid  = tid >> 5;
    int i = blockIdx.x * SCAN_BLK + tid;
    int c = (i < NNODES) ? g_cnt[i] : 0;
    if (i < NNODES) g_dinv[i] = rsqrtf((float)c + 1.0f);

    int x = c;
    #pragma unroll
    for (int o = 16; o > 0; o >>= 1) x += __shfl_down_sync(0xffffffffu, x, o);
    if (lane == 0) warp_sums[wid] = x;
    __syncthreads();
    if (wid == 0) {
        int s = warp_sums[lane];
        #pragma unroll
        for (int o = 16; o > 0; o >>= 1) s += __shfl_down_sync(0xffffffffu, s, o);
        if (lane == 0) g_bsum[blockIdx.x] = s;
    }
}

// phase 2: exclusive scan of the 49 block sums (one 64-thread block)
__global__ void k_scan_bsum() {
    __shared__ int ws[2];
    const int tid  = threadIdx.x;   // 64
    const int lane = tid & 31;
    const int w    = tid >> 5;
    int v = (tid < NSCANBLK) ? g_bsum[tid] : 0;
    int x = v;
    #pragma unroll
    for (int o = 1; o < 32; o <<= 1) {
        int y = __shfl_up_sync(0xffffffffu, x, o);
        if (lane >= o) x += y;
    }
    if (lane == 31) ws[w] = x;
    __syncthreads();
    int incl = x + ((w == 1) ? ws[0] : 0);
    if (tid < NSCANBLK) g_bsum[tid] = incl - v;   // exclusive
    if (tid == 0) g_rowptr[NNODES] = NEDGES;
}

// phase 3: per-block scan + offset -> rowptr / pos
__global__ void k_scan_apply() {
    __shared__ int warp_sums[32];
    const int tid  = threadIdx.x;
    const int lane = tid & 31;
    const int wid  = tid >> 5;
    int i = blockIdx.x * SCAN_BLK + tid;
    int v = (i < NNODES) ? g_cnt[i] : 0;

    int x = v;
    #pragma unroll
    for (int o = 1; o < 32; o <<= 1) {
        int y = __shfl_up_sync(0xffffffffu, x, o);
        if (lane >= o) x += y;
    }
    if (lane == 31) warp_sums[wid] = x;
    __syncthreads();
    if (wid == 0) {
        int s = warp_sums[lane];
        #pragma unroll
        for (int o = 1; o < 32; o <<= 1) {
            int y = __shfl_up_sync(0xffffffffu, s, o);
            if (lane >= o) s += y;
        }
        warp_sums[lane] = s;
    }
    __syncthreads();
    int excl = g_bsum[blockIdx.x] + x - v + (wid > 0 ? warp_sums[wid - 1] : 0);
    if (i < NNODES) { g_rowptr[i] = excl; g_pos[i] = excl; }
}

__global__ void k_scatter(const int* __restrict__ row, const int* __restrict__ col) {
    int e = blockIdx.x * blockDim.x + threadIdx.x;
    if (e < NEDGES) {
        int c = col[e];
        int r = row[e];
        int p = atomicAdd(&g_pos[c], 1);
        g_srow[p]  = r;
        g_sdinv[p] = g_dinv[r];
    }
}

// ---------------- SGEMM: C[M,BN] = A[M,HID] @ W[HID,BN] (+ bias) ----------------
// BM=128, BK=16, TM=8; 256 threads; BN in {128, 64}, TN = BN/16.
template <int BN, int TN>
__global__ void k_gemm(const float* __restrict__ A,
                       const float* __restrict__ W,
                       const float* __restrict__ bias,   // nullptr -> no bias
                       float* __restrict__ C,
                       int M) {
    constexpr int BM = 128;
    constexpr int BK = 16;
    constexpr int TM = 8;
    __shared__ __align__(16) float As[BK][BM];
    __shared__ __align__(16) float Bs[BK][BN];

    const int tid = threadIdx.x;             // 0..255
    const int tx  = tid & 15;                // col group
    const int ty  = tid >> 4;                // row group
    const int rowBase = blockIdx.x * BM;

    float acc[TM][TN];
    #pragma unroll
    for (int i = 0; i < TM; i++)
        #pragma unroll
        for (int j = 0; j < TN; j++) acc[i][j] = 0.0f;

    for (int k0 = 0; k0 < HID; k0 += BK) {
        // --- load A tile (BM x BK), store transposed As[k][m] ---
        #pragma unroll
        for (int i = 0; i < 2; i++) {
            int idx = tid + i * 256;                 // 0..511 float4 id
            int r   = idx >> 2;                      // 0..127
            int c4  = (idx & 3) * 4;                 // 0,4,8,12
            float4 v = make_float4(0.f, 0.f, 0.f, 0.f);
            int gr = rowBase + r;
            if (gr < M)
                v = *reinterpret_cast<const float4*>(A + (size_t)gr * HID + k0 + c4);
            As[c4 + 0][r] = v.x;
            As[c4 + 1][r] = v.y;
            As[c4 + 2][r] = v.z;
            As[c4 + 3][r] = v.w;
        }
        // --- load B tile (BK x BN) ---
        constexpr int B4 = (BK * BN) / 4;            // float4 count
        #pragma unroll
        for (int i = 0; i < B4 / 256; i++) {
            int idx = tid + i * 256;
            int r   = idx / (BN / 4);
            int c4  = (idx % (BN / 4)) * 4;
            float4 v = *reinterpret_cast<const float4*>(W + (size_t)(k0 + r) * BN + c4);
            *reinterpret_cast<float4*>(&Bs[r][c4]) = v;
        }
        __syncthreads();

        #pragma unroll
        for (int k = 0; k < BK; k++) {
            float a[TM], b[TN];
            #pragma unroll
            for (int i = 0; i < TM; i += 4)
                *reinterpret_cast<float4*>(&a[i]) =
                    *reinterpret_cast<const float4*>(&As[k][ty * TM + i]);
            #pragma unroll
            for (int j = 0; j < TN; j += 4)
                *reinterpret_cast<float4*>(&b[j]) =
                    *reinterpret_cast<const float4*>(&Bs[k][tx * TN + j]);
            #pragma unroll
            for (int i = 0; i < TM; i++)
                #pragma unroll
                for (int j = 0; j < TN; j++)
                    acc[i][j] += a[i] * b[j];
        }
        __syncthreads();
    }

    float bv[TN];
    #pragma unroll
    for (int j = 0; j < TN; j++) bv[j] = bias ? bias[tx * TN + j] : 0.0f;

    #pragma unroll
    for (int i = 0; i < TM; i++) {
        int gr = rowBase + ty * TM + i;
        if (gr < M) {
            #pragma unroll
            for (int j = 0; j < TN; j += 4) {
                float4 v = make_float4(acc[i][j] + bv[j],
                                       acc[i][j + 1] + bv[j + 1],
                                       acc[i][j + 2] + bv[j + 2],
                                       acc[i][j + 3] + bv[j + 3]);
                *reinterpret_cast<float4*>(C + (size_t)gr * BN + tx * TN + j) = v;
            }
        }
    }
}

// ---------------- neighbor aggregation (+self loop, +bias, ReLU) ----------------
// one warp per node; lane handles 4 contiguous features (float4)
__global__ void k_agg(const float* __restrict__ h,
                      const float* __restrict__ bias,
                      float* __restrict__ out) {
    int gwarp = (blockIdx.x * blockDim.x + threadIdx.x) >> 5;
    int lane  = threadIdx.x & 31;
    if (gwarp >= NNODES) return;
    const int n = gwarp;

    const float dn = g_dinv[n];
    float4 acc = *reinterpret_cast<const float4*>(h + (size_t)n * HID + lane * 4);
    const float sn = dn * dn;
    acc.x *= sn; acc.y *= sn; acc.z *= sn; acc.w *= sn;

    const int beg = g_rowptr[n];
    const int end = g_rowptr[n + 1];

    int e = beg;
    int   r_next = (e < end) ? g_srow[e]  : 0;
    float d_next = (e < end) ? g_sdinv[e] : 0.0f;
    while (e < end) {
        int   r  = r_next;
        float dr = d_next;
        ++e;
        if (e < end) { r_next = g_srow[e]; d_next = g_sdinv[e]; }
        float w = dr * dn;
        float4 hv = *reinterpret_cast<const float4*>(h + (size_t)r * HID + lane * 4);
        acc.x += hv.x * w;
        acc.y += hv.y * w;
        acc.z += hv.z * w;
        acc.w += hv.w * w;
    }

    float4 b = *reinterpret_cast<const float4*>(bias + lane * 4);
    acc.x = fmaxf(acc.x + b.x, 0.0f);
    acc.y = fmaxf(acc.y + b.y, 0.0f);
    acc.z = fmaxf(acc.z + b.z, 0.0f);
    acc.w = fmaxf(acc.w + b.w, 0.0f);
    *reinterpret_cast<float4*>(out + (size_t)n * HID + lane * 4) = acc;
}

// ---------------- launch ----------------
extern "C" void kernel_launch(void* const* d_in, const int* in_sizes, int n_in,
                              void* d_out, int out_size) {
    const float* x    = (const float*)d_in[0];
    const int*   ei   = (const int*)d_in[1];
    const int*   row  = ei;
    const int*   col  = ei + NEDGES;
    const float* W0   = (const float*)d_in[2];
    const float* b0   = (const float*)d_in[3];
    const float* W1   = (const float*)d_in[4];
    const float* b1   = (const float*)d_in[5];
    const float* W2   = (const float*)d_in[6];
    const float* b2   = (const float*)d_in[7];
    const float* Wlin = (const float*)d_in[8];
    const float* blin = (const float*)d_in[9];
    float* out = (float*)d_out;

    float *bufA, *bufB;
    cudaGetSymbolAddress((void**)&bufA, g_bufA);
    cudaGetSymbolAddress((void**)&bufB, g_bufB);
    int* cntPtr;
    cudaGetSymbolAddress((void**)&cntPtr, g_cnt);

    // preprocessing (per launch; graph is input-dependent)
    cudaMemsetAsync(cntPtr, 0, NNODES * sizeof(int));
    k_count<<<(NEDGES + 255) / 256, 256>>>(col);
    k_sum_dinv<<<NSCANBLK, SCAN_BLK>>>();
    k_scan_bsum<<<1, 64>>>();
    k_scan_apply<<<NSCANBLK, SCAN_BLK>>>();
    k_scatter<<<(NEDGES + 255) / 256, 256>>>(row, col);

    const int gemm_blocks = (NNODES + 127) / 128;
    const int agg_blocks  = (NNODES * 32 + 255) / 256;

    // layer 0
    k_gemm<128, 8><<<gemm_blocks, 256>>>(x, W0, nullptr, bufA, NNODES);
    k_agg<<<agg_blocks, 256>>>(bufA, b0, bufB);
    // layer 1
    k_gemm<128, 8><<<gemm_blocks, 256>>>(bufB, W1, nullptr, bufA, NNODES);
    k_agg<<<agg_blocks, 256>>>(bufA, b1, bufB);
    // layer 2
    k_gemm<128, 8><<<gemm_blocks, 256>>>(bufB, W2, nullptr, bufA, NNODES);
    k_agg<<<agg_blocks, 256>>>(bufA, b2, bufB);
    // output head
    k_gemm<64, 4><<<gemm_blocks, 256>>>(bufB, Wlin, blin, out, NNODES);
}

// round 5
// speedup vs baseline: 2.1089x; 1.3632x over previous
#include <cuda_runtime.h>
#include <cuda_bf16.h>
#include <cstdint>

#define NNODES 50000
#define NEDGES 640000
#define HID    128
#define CLS    64
#define NT     391            // ceil(50000/128) M-tiles

#define SCAN_BLK 1024
#define NSCANBLK ((NNODES + SCAN_BLK - 1) / SCAN_BLK)   // 49

typedef unsigned long long u64;

// ---------------- scratch (static __device__, no allocation) ----------------
__device__ float g_h[NNODES * HID];                        // fp32 hidden
__device__ __align__(16) __nv_bfloat16 g_Ahi[NT * 16384];  // A tiles, ldmatrix layout
__device__ __align__(16) __nv_bfloat16 g_Alo[NT * 16384];
__device__ __align__(16) unsigned char g_Whi[3 * 32768 + 16384]; // W^T tiles
__device__ __align__(16) unsigned char g_Wlo[3 * 32768 + 16384];
__device__ float g_dinv[NNODES];
__device__ int   g_cnt[NNODES];
__device__ int   g_rowptr[NNODES + 1];
__device__ int   g_pos[NNODES];
__device__ int   g_bsum[NSCANBLK];
__device__ int   g_srow[NEDGES];
__device__ float g_sdinv[NEDGES];

// ---------------- helpers ----------------
__device__ __forceinline__ uint32_t smem_to_u32(const void* p) {
    uint32_t a;
    asm("{ .reg .u64 t; cvta.to.shared.u64 t, %1; cvt.u32.u64 %0, t; }" : "=r"(a) : "l"(p));
    return a;
}

// tile layout: 128-bf16 rows (256B), 16B chunks XOR-swizzled by row for
// conflict-free ldmatrix. byte(r, k) = r*256 + 16*((k>>3) ^ (r&7)) + (k&7)*2
__device__ __forceinline__ uint32_t tile_off(int r, int k) {
    return (uint32_t)(r * 256 + 16 * (((k >> 3) ^ (r & 7))) + (k & 7) * 2);
}

__device__ __forceinline__ void ldsm4(uint32_t* r, uint32_t addr) {
    asm volatile("ldmatrix.sync.aligned.m8n8.x4.shared.b16 {%0,%1,%2,%3}, [%4];"
                 : "=r"(r[0]), "=r"(r[1]), "=r"(r[2]), "=r"(r[3]) : "r"(addr));
}
__device__ __forceinline__ void mma16816(float* c, const uint32_t* a, const uint32_t* b) {
    asm volatile("mma.sync.aligned.m16n8k16.row.col.f32.bf16.bf16.f32 "
                 "{%0,%1,%2,%3}, {%4,%5,%6,%7}, {%8,%9}, {%0,%1,%2,%3};"
                 : "+f"(c[0]), "+f"(c[1]), "+f"(c[2]), "+f"(c[3])
                 : "r"(a[0]), "r"(a[1]), "r"(a[2]), "r"(a[3]), "r"(b[0]), "r"(b[1]));
}

// split one float4 into hi/lo bf16x4 and store 8B each (ldmatrix layout)
__device__ __forceinline__ void split_store(char* hiB, char* loB, uint32_t off, float4 v) {
    __nv_bfloat162 h0 = __floats2bfloat162_rn(v.x, v.y);
    __nv_bfloat162 h1 = __floats2bfloat162_rn(v.z, v.w);
    float rx = v.x - __low2float(h0);
    float ry = v.y - __high2float(h0);
    float rz = v.z - __low2float(h1);
    float rw = v.w - __high2float(h1);
    __nv_bfloat162 l0 = __floats2bfloat162_rn(rx, ry);
    __nv_bfloat162 l1 = __floats2bfloat162_rn(rz, rw);
    uint2 hu = make_uint2(*(uint32_t*)&h0, *(uint32_t*)&h1);
    uint2 lu = make_uint2(*(uint32_t*)&l0, *(uint32_t*)&l1);
    *reinterpret_cast<uint2*>(hiB + off) = hu;
    *reinterpret_cast<uint2*>(loB + off) = lu;
}

// ---------------- preprocessing ----------------
__global__ void k_count(const int* __restrict__ col) {
    int e = blockIdx.x * blockDim.x + threadIdx.x;
    if (e < NEDGES) atomicAdd(&g_cnt[col[e]], 1);
}

__global__ void k_sum_dinv() {
    __shared__ int warp_sums[32];
    const int tid  = threadIdx.x;
    const int lane = tid & 31;
    const int wid  = tid >> 5;
    int i = blockIdx.x * SCAN_BLK + tid;
    int c = (i < NNODES) ? g_cnt[i] : 0;
    if (i < NNODES) g_dinv[i] = rsqrtf((float)c + 1.0f);
    int x = c;
    #pragma unroll
    for (int o = 16; o > 0; o >>= 1) x += __shfl_down_sync(0xffffffffu, x, o);
    if (lane == 0) warp_sums[wid] = x;
    __syncthreads();
    if (wid == 0) {
        int s = warp_sums[lane];
        #pragma unroll
        for (int o = 16; o > 0; o >>= 1) s += __shfl_down_sync(0xffffffffu, s, o);
        if (lane == 0) g_bsum[blockIdx.x] = s;
    }
}

__global__ void k_scan_bsum() {
    __shared__ int ws[2];
    const int tid  = threadIdx.x;   // 64
    const int lane = tid & 31;
    const int w    = tid >> 5;
    int v = (tid < NSCANBLK) ? g_bsum[tid] : 0;
    int x = v;
    #pragma unroll
    for (int o = 1; o < 32; o <<= 1) {
        int y = __shfl_up_sync(0xffffffffu, x, o);
        if (lane >= o) x += y;
    }
    if (lane == 31) ws[w] = x;
    __syncthreads();
    int incl = x + ((w == 1) ? ws[0] : 0);
    if (tid < NSCANBLK) g_bsum[tid] = incl - v;
    if (tid == 0) g_rowptr[NNODES] = NEDGES;
}

__global__ void k_scan_apply() {
    __shared__ int warp_sums[32];
    const int tid  = threadIdx.x;
    const int lane = tid & 31;
    const int wid  = tid >> 5;
    int i = blockIdx.x * SCAN_BLK + tid;
    int v = (i < NNODES) ? g_cnt[i] : 0;
    int x = v;
    #pragma unroll
    for (int o = 1; o < 32; o <<= 1) {
        int y = __shfl_up_sync(0xffffffffu, x, o);
        if (lane >= o) x += y;
    }
    if (lane == 31) warp_sums[wid] = x;
    __syncthreads();
    if (wid == 0) {
        int s = warp_sums[lane];
        #pragma unroll
        for (int o = 1; o < 32; o <<= 1) {
            int y = __shfl_up_sync(0xffffffffu, s, o);
            if (lane >= o) s += y;
        }
        warp_sums[lane] = s;
    }
    __syncthreads();
    int excl = g_bsum[blockIdx.x] + x - v + (wid > 0 ? warp_sums[wid - 1] : 0);
    if (i < NNODES) { g_rowptr[i] = excl; g_pos[i] = excl; }
}

__global__ void k_scatter(const int* __restrict__ row, const int* __restrict__ col) {
    int e = blockIdx.x * blockDim.x + threadIdx.x;
    if (e < NEDGES) {
        int c = col[e];
        int r = row[e];
        int p = atomicAdd(&g_pos[c], 1);
        g_srow[p]  = r;
        g_sdinv[p] = g_dinv[r];
    }
}

// ---------------- weight prep: W[K,N] -> W^T[N,K] tiles, hi/lo ----------------
__global__ void k_wprep(const float* __restrict__ W0, const float* __restrict__ W1,
                        const float* __restrict__ W2, const float* __restrict__ Wlin) {
    int idx = blockIdx.x * blockDim.x + threadIdx.x;   // 0 .. 57343
    if (idx >= 3 * 16384 + 8192) return;
    float w;
    uint32_t dst;
    if (idx < 3 * 16384) {
        int g = idx >> 14;
        int rem = idx & 16383;
        int k = rem >> 7;
        int n = rem & 127;
        const float* W = (g == 0) ? W0 : (g == 1) ? W1 : W2;
        w = W[k * 128 + n];
        dst = g * 32768 + tile_off(n, k);
    } else {
        int rem = idx - 3 * 16384;     // 0..8191
        int k = rem >> 6;
        int n = rem & 63;
        w = Wlin[k * 64 + n];
        dst = 3 * 32768 + tile_off(n, k);
    }
    __nv_bfloat16 hi = __float2bfloat16_rn(w);
    float lo = w - __bfloat162float(hi);
    *reinterpret_cast<__nv_bfloat16*>(g_Whi + dst) = hi;
    *reinterpret_cast<__nv_bfloat16*>(g_Wlo + dst) = __float2bfloat16_rn(lo);
}

// ---------------- convert x -> A tiles (hi/lo, ldmatrix layout) ----------------
__global__ void k_convert_x(const float* __restrict__ x) {
    int gwarp = (blockIdx.x * blockDim.x + threadIdx.x) >> 5;
    int lane  = threadIdx.x & 31;
    if (gwarp >= NNODES) return;
    float4 v = *reinterpret_cast<const float4*>(x + (size_t)gwarp * HID + lane * 4);
    int tile = gwarp >> 7, r = gwarp & 127;
    uint32_t off = tile_off(r, lane * 4);
    split_store((char*)g_Ahi + (size_t)tile * 32768,
                (char*)g_Alo + (size_t)tile * 32768, off, v);
}

// ---------------- tensor-core GEMM via mma.sync, split-bf16 x3 passes ----------
// C[M, NCOLS] = A[M,128] @ W[128,NCOLS]; 256 threads, warp tile 32 x NCOLS/2.
template <int NCOLS>
__global__ __launch_bounds__(256, 1)
void k_gemm_mma(const uint4* __restrict__ Bhi4, const uint4* __restrict__ Blo4,
                const float* __restrict__ bias, float* __restrict__ C) {
    constexpr int A_BYTES = 32768;                 // 128 rows x 256B
    constexpr int B_BYTES = NCOLS * 256;           // NCOLS rows x 256B
    constexpr int OFF_AHI = 0;
    constexpr int OFF_ALO = A_BYTES;
    constexpr int OFF_BHI = 2 * A_BYTES;
    constexpr int OFF_BLO = 2 * A_BYTES + B_BYTES;
    constexpr int NT8 = NCOLS / 16;                // n-tiles (of 8) per warp
    extern __shared__ __align__(16) char smem[];

    const int tid  = threadIdx.x;
    const int wid  = tid >> 5;
    const int lane = tid & 31;
    const int tile = blockIdx.x;

    // identity copies (gmem already in ldmatrix tile layout)
    {
        const uint4* srcH = reinterpret_cast<const uint4*>((const char*)g_Ahi + (size_t)tile * A_BYTES);
        const uint4* srcL = reinterpret_cast<const uint4*>((const char*)g_Alo + (size_t)tile * A_BYTES);
        uint4* dH = reinterpret_cast<uint4*>(smem + OFF_AHI);
        uint4* dL = reinterpret_cast<uint4*>(smem + OFF_ALO);
        #pragma unroll
        for (int i = tid; i < A_BYTES / 16; i += 256) { dH[i] = srcH[i]; dL[i] = srcL[i]; }
        uint4* bH = reinterpret_cast<uint4*>(smem + OFF_BHI);
        uint4* bL = reinterpret_cast<uint4*>(smem + OFF_BLO);
        #pragma unroll
        for (int i = tid; i < B_BYTES / 16; i += 256) { bH[i] = Bhi4[i]; bL[i] = Blo4[i]; }
    }
    __syncthreads();

    const int wm  = wid >> 1;                 // 0..3
    const int wn  = wid & 1;                  // 0..1
    const int m0w = wm * 32;
    const int n0w = wn * (NCOLS / 2);

    float acc[2][NT8][4];
    #pragma unroll
    for (int mi = 0; mi < 2; mi++)
        #pragma unroll
        for (int ni = 0; ni < NT8; ni++)
            #pragma unroll
            for (int q = 0; q < 4; q++) acc[mi][ni][q] = 0.0f;

    const uint32_t sb = smem_to_u32(smem);
    const int arow    = m0w + (lane & 15);
    const int asw     = arow & 7;
    const int akc_add = lane >> 4;
    const int bn      = n0w + (lane & 7) + ((lane >> 4) << 3);
    const int bsw     = bn & 7;
    const int bkc_add = (lane >> 3) & 1;

    #pragma unroll
    for (int pass = 0; pass < 3; pass++) {
        const uint32_t Ab = sb + ((pass == 2) ? OFF_ALO : OFF_AHI);
        const uint32_t Bb = sb + ((pass == 1) ? OFF_BLO : OFF_BHI);
        #pragma unroll
        for (int s = 0; s < 8; s++) {
            const int kca = 2 * s + akc_add;
            const int kcb = 2 * s + bkc_add;
            uint32_t a[2][4];
            #pragma unroll
            for (int mi = 0; mi < 2; mi++)
                ldsm4(a[mi], Ab + (uint32_t)((arow + mi * 16) * 256 + 16 * (kca ^ asw)));
            uint32_t b[NT8][2];
            #pragma unroll
            for (int nj = 0; nj < NT8 / 2; nj++) {
                uint32_t r[4];
                ldsm4(r, Bb + (uint32_t)((bn + nj * 16) * 256 + 16 * (kcb ^ bsw)));
                b[2 * nj][0] = r[0]; b[2 * nj][1] = r[1];
                b[2 * nj + 1][0] = r[2]; b[2 * nj + 1][1] = r[3];
            }
            #pragma unroll
            for (int mi = 0; mi < 2; mi++)
                #pragma unroll
                for (int ni = 0; ni < NT8; ni++)
                    mma16816(acc[mi][ni], a[mi], b[ni]);
        }
    }

    // epilogue: fragment c: lane l -> rows (l>>2), (l>>2)+8; cols (l&3)*2, +1
    const int rbase = tile * 128 + m0w;
    #pragma unroll
    for (int mi = 0; mi < 2; mi++) {
        int r0 = rbase + mi * 16 + (lane >> 2);
        int r1 = r0 + 8;
        #pragma unroll
        for (int ni = 0; ni < NT8; ni++) {
            int c = n0w + ni * 8 + (lane & 3) * 2;
            float bx = 0.f, by = 0.f;
            if (bias) { bx = bias[c]; by = bias[c + 1]; }
            if (r0 < NNODES) {
                float2 v = make_float2(acc[mi][ni][0] + bx, acc[mi][ni][1] + by);
                *reinterpret_cast<float2*>(C + (size_t)r0 * NCOLS + c) = v;
            }
            if (r1 < NNODES) {
                float2 v = make_float2(acc[mi][ni][2] + bx, acc[mi][ni][3] + by);
                *reinterpret_cast<float2*>(C + (size_t)r1 * NCOLS + c) = v;
            }
        }
    }
}

// ---------------- aggregation: gather fp32 h, norms+bias+relu, emit A tiles ----
__global__ void k_agg(const float* __restrict__ h,
                      const float* __restrict__ bias) {
    int gwarp = (blockIdx.x * blockDim.x + threadIdx.x) >> 5;
    int lane  = threadIdx.x & 31;
    if (gwarp >= NNODES) return;
    const int n = gwarp;

    const float dn = g_dinv[n];
    float4 acc = *reinterpret_cast<const float4*>(h + (size_t)n * HID + lane * 4);
    const float sn = dn * dn;
    acc.x *= sn; acc.y *= sn; acc.z *= sn; acc.w *= sn;

    const int beg = g_rowptr[n];
    const int end = g_rowptr[n + 1];
    int e = beg;
    int   r_next = (e < end) ? g_srow[e]  : 0;
    float d_next = (e < end) ? g_sdinv[e] : 0.0f;
    while (e < end) {
        int   r  = r_next;
        float dr = d_next;
        ++e;
        if (e < end) { r_next = g_srow[e]; d_next = g_sdinv[e]; }
        float w = dr * dn;
        float4 hv = *reinterpret_cast<const float4*>(h + (size_t)r * HID + lane * 4);
        acc.x += hv.x * w;
        acc.y += hv.y * w;
        acc.z += hv.z * w;
        acc.w += hv.w * w;
    }

    float4 b = *reinterpret_cast<const float4*>(bias + lane * 4);
    acc.x = fmaxf(acc.x + b.x, 0.0f);
    acc.y = fmaxf(acc.y + b.y, 0.0f);
    acc.z = fmaxf(acc.z + b.z, 0.0f);
    acc.w = fmaxf(acc.w + b.w, 0.0f);

    int tile = n >> 7, r = n & 127;
    uint32_t off = tile_off(r, lane * 4);
    split_store((char*)g_Ahi + (size_t)tile * 32768,
                (char*)g_Alo + (size_t)tile * 32768, off, acc);
}

// ---------------- launch ----------------
extern "C" void kernel_launch(void* const* d_in, const int* in_sizes, int n_in,
                              void* d_out, int out_size) {
    const float* x    = (const float*)d_in[0];
    const int*   ei   = (const int*)d_in[1];
    const int*   row  = ei;
    const int*   col  = ei + NEDGES;
    const float* W0   = (const float*)d_in[2];
    const float* b0   = (const float*)d_in[3];
    const float* W1   = (const float*)d_in[4];
    const float* b1   = (const float*)d_in[5];
    const float* W2   = (const float*)d_in[6];
    const float* b2   = (const float*)d_in[7];
    const float* Wlin = (const float*)d_in[8];
    const float* blin = (const float*)d_in[9];
    float* out = (float*)d_out;

    float* hPtr;   cudaGetSymbolAddress((void**)&hPtr, g_h);
    int*   cntPtr; cudaGetSymbolAddress((void**)&cntPtr, g_cnt);
    unsigned char *whi, *wlo;
    cudaGetSymbolAddress((void**)&whi, g_Whi);
    cudaGetSymbolAddress((void**)&wlo, g_Wlo);

    constexpr int SMEM_128 = 2 * 32768 + 2 * 32768;  // 131072
    constexpr int SMEM_64  = 2 * 32768 + 2 * 16384;  //  98304
    cudaFuncSetAttribute(k_gemm_mma<128>, cudaFuncAttributeMaxDynamicSharedMemorySize, SMEM_128);
    cudaFuncSetAttribute(k_gemm_mma<64>,  cudaFuncAttributeMaxDynamicSharedMemorySize, SMEM_64);

    // preprocessing
    cudaMemsetAsync(cntPtr, 0, NNODES * sizeof(int));
    k_count<<<(NEDGES + 255) / 256, 256>>>(col);
    k_sum_dinv<<<NSCANBLK, SCAN_BLK>>>();
    k_scan_bsum<<<1, 64>>>();
    k_scan_apply<<<NSCANBLK, SCAN_BLK>>>();
    k_scatter<<<(NEDGES + 255) / 256, 256>>>(row, col);
    k_wprep<<<(3 * 16384 + 8192 + 255) / 256, 256>>>(W0, W1, W2, Wlin);
    k_convert_x<<<(NNODES * 32 + 255) / 256, 256>>>(x);

    const int agg_blocks = (NNODES * 32 + 255) / 256;

    // layer 0
    k_gemm_mma<128><<<NT, 256, SMEM_128>>>((const uint4*)(whi + 0 * 32768),
                                           (const uint4*)(wlo + 0 * 32768), nullptr, hPtr);
    k_agg<<<agg_blocks, 256>>>(hPtr, b0);
    // layer 1
    k_gemm_mma<128><<<NT, 256, SMEM_128>>>((const uint4*)(whi + 1 * 32768),
                                           (const uint4*)(wlo + 1 * 32768), nullptr, hPtr);
    k_agg<<<agg_blocks, 256>>>(hPtr, b1);
    // layer 2
    k_gemm_mma<128><<<NT, 256, SMEM_128>>>((const uint4*)(whi + 2 * 32768),
                                           (const uint4*)(wlo + 2 * 32768), nullptr, hPtr);
    k_agg<<<agg_blocks, 256>>>(hPtr, b2);
    // head
    k_gemm_mma<64><<<NT, 256, SMEM_64>>>((const uint4*)(whi + 3 * 32768),
                                         (const uint4*)(wlo + 3 * 32768), blin, out);
}

// round 6
// speedup vs baseline: 2.2605x; 1.0719x over previous
#include <cuda_runtime.h>
#include <cuda_bf16.h>
#include <cstdint>

#define NNODES 50000
#define NEDGES 640000
#define HID    128
#define CLS    64
#define NT     391            // ceil(50000/128) M-tiles

#define SCAN_BLK 1024
#define NSCANBLK ((NNODES + SCAN_BLK - 1) / SCAN_BLK)   // 49

typedef unsigned long long u64;

// ---------------- scratch (static __device__, no allocation) ----------------
__device__ float g_h[NNODES * HID];                        // fp32 hidden
__device__ __align__(16) __nv_bfloat16 g_Ahi[NT * 16384];  // A tiles, ldmatrix layout
__device__ __align__(16) __nv_bfloat16 g_Alo[NT * 16384];
__device__ __align__(16) unsigned char g_Whi[3 * 32768 + 16384]; // W^T tiles
__device__ __align__(16) unsigned char g_Wlo[3 * 32768 + 16384];
__device__ float g_dinv[NNODES];
__device__ int   g_cnt[NNODES];
__device__ int   g_rowptr[NNODES + 1];
__device__ int   g_pos[NNODES];
__device__ int   g_bsum[NSCANBLK];
__device__ int   g_srow[NEDGES];
__device__ float g_sdinv[NEDGES];

// ---------------- helpers ----------------
__device__ __forceinline__ uint32_t smem_to_u32(const void* p) {
    uint32_t a;
    asm("{ .reg .u64 t; cvta.to.shared.u64 t, %1; cvt.u32.u64 %0, t; }" : "=r"(a) : "l"(p));
    return a;
}

// tile layout: 128-bf16 rows (256B), 16B chunks XOR-swizzled by row for
// conflict-free ldmatrix. byte(r, k) = r*256 + 16*((k>>3) ^ (r&7)) + (k&7)*2
__device__ __forceinline__ uint32_t tile_off(int r, int k) {
    return (uint32_t)(r * 256 + 16 * (((k >> 3) ^ (r & 7))) + (k & 7) * 2);
}

__device__ __forceinline__ void ldsm4(uint32_t* r, uint32_t addr) {
    asm volatile("ldmatrix.sync.aligned.m8n8.x4.shared.b16 {%0,%1,%2,%3}, [%4];"
                 : "=r"(r[0]), "=r"(r[1]), "=r"(r[2]), "=r"(r[3]) : "r"(addr));
}
__device__ __forceinline__ void mma16816(float* c, const uint32_t* a, const uint32_t* b) {
    asm volatile("mma.sync.aligned.m16n8k16.row.col.f32.bf16.bf16.f32 "
                 "{%0,%1,%2,%3}, {%4,%5,%6,%7}, {%8,%9}, {%0,%1,%2,%3};"
                 : "+f"(c[0]), "+f"(c[1]), "+f"(c[2]), "+f"(c[3])
                 : "r"(a[0]), "r"(a[1]), "r"(a[2]), "r"(a[3]), "r"(b[0]), "r"(b[1]));
}

// split one float4 into hi/lo bf16x4 and store 8B each (ldmatrix layout)
__device__ __forceinline__ void split_store(char* hiB, char* loB, uint32_t off, float4 v) {
    __nv_bfloat162 h0 = __floats2bfloat162_rn(v.x, v.y);
    __nv_bfloat162 h1 = __floats2bfloat162_rn(v.z, v.w);
    float rx = v.x - __low2float(h0);
    float ry = v.y - __high2float(h0);
    float rz = v.z - __low2float(h1);
    float rw = v.w - __high2float(h1);
    __nv_bfloat162 l0 = __floats2bfloat162_rn(rx, ry);
    __nv_bfloat162 l1 = __floats2bfloat162_rn(rz, rw);
    uint2 hu = make_uint2(*(uint32_t*)&h0, *(uint32_t*)&h1);
    uint2 lu = make_uint2(*(uint32_t*)&l0, *(uint32_t*)&l1);
    *reinterpret_cast<uint2*>(hiB + off) = hu;
    *reinterpret_cast<uint2*>(loB + off) = lu;
}

// ---------------- preprocessing ----------------
__global__ void k_count(const int* __restrict__ col) {
    int e = blockIdx.x * blockDim.x + threadIdx.x;
    if (e < NEDGES) atomicAdd(&g_cnt[col[e]], 1);
}

__global__ void k_sum_dinv() {
    __shared__ int warp_sums[32];
    const int tid  = threadIdx.x;
    const int lane = tid & 31;
    const int wid  = tid >> 5;
    int i = blockIdx.x * SCAN_BLK + tid;
    int c = (i < NNODES) ? g_cnt[i] : 0;
    if (i < NNODES) g_dinv[i] = rsqrtf((float)c + 1.0f);
    int x = c;
    #pragma unroll
    for (int o = 16; o > 0; o >>= 1) x += __shfl_down_sync(0xffffffffu, x, o);
    if (lane == 0) warp_sums[wid] = x;
    __syncthreads();
    if (wid == 0) {
        int s = warp_sums[lane];
        #pragma unroll
        for (int o = 16; o > 0; o >>= 1) s += __shfl_down_sync(0xffffffffu, s, o);
        if (lane == 0) g_bsum[blockIdx.x] = s;
    }
}

__global__ void k_scan_bsum() {
    __shared__ int ws[2];
    const int tid  = threadIdx.x;   // 64
    const int lane = tid & 31;
    const int w    = tid >> 5;
    int v = (tid < NSCANBLK) ? g_bsum[tid] : 0;
    int x = v;
    #pragma unroll
    for (int o = 1; o < 32; o <<= 1) {
        int y = __shfl_up_sync(0xffffffffu, x, o);
        if (lane >= o) x += y;
    }
    if (lane == 31) ws[w] = x;
    __syncthreads();
    int incl = x + ((w == 1) ? ws[0] : 0);
    if (tid < NSCANBLK) g_bsum[tid] = incl - v;
    if (tid == 0) g_rowptr[NNODES] = NEDGES;
}

__global__ void k_scan_apply() {
    __shared__ int warp_sums[32];
    const int tid  = threadIdx.x;
    const int lane = tid & 31;
    const int wid  = tid >> 5;
    int i = blockIdx.x * SCAN_BLK + tid;
    int v = (i < NNODES) ? g_cnt[i] : 0;
    int x = v;
    #pragma unroll
    for (int o = 1; o < 32; o <<= 1) {
        int y = __shfl_up_sync(0xffffffffu, x, o);
        if (lane >= o) x += y;
    }
    if (lane == 31) warp_sums[wid] = x;
    __syncthreads();
    if (wid == 0) {
        int s = warp_sums[lane];
        #pragma unroll
        for (int o = 1; o < 32; o <<= 1) {
            int y = __shfl_up_sync(0xffffffffu, s, o);
            if (lane >= o) s += y;
        }
        warp_sums[lane] = s;
    }
    __syncthreads();
    int excl = g_bsum[blockIdx.x] + x - v + (wid > 0 ? warp_sums[wid - 1] : 0);
    if (i < NNODES) { g_rowptr[i] = excl; g_pos[i] = excl; }
}

__global__ void k_scatter(const int* __restrict__ row, const int* __restrict__ col) {
    int e = blockIdx.x * blockDim.x + threadIdx.x;
    if (e < NEDGES) {
        int c = col[e];
        int r = row[e];
        int p = atomicAdd(&g_pos[c], 1);
        g_srow[p]  = r;
        g_sdinv[p] = g_dinv[r];
    }
}

// ---------------- weight prep: W[K,N] -> W^T[N,K] tiles, hi/lo ----------------
__global__ void k_wprep(const float* __restrict__ W0, const float* __restrict__ W1,
                        const float* __restrict__ W2, const float* __restrict__ Wlin) {
    int idx = blockIdx.x * blockDim.x + threadIdx.x;   // 0 .. 57343
    if (idx >= 3 * 16384 + 8192) return;
    float w;
    uint32_t dst;
    if (idx < 3 * 16384) {
        int g = idx >> 14;
        int rem = idx & 16383;
        int k = rem >> 7;
        int n = rem & 127;
        const float* W = (g == 0) ? W0 : (g == 1) ? W1 : W2;
        w = W[k * 128 + n];
        dst = g * 32768 + tile_off(n, k);
    } else {
        int rem = idx - 3 * 16384;     // 0..8191
        int k = rem >> 6;
        int n = rem & 63;
        w = Wlin[k * 64 + n];
        dst = 3 * 32768 + tile_off(n, k);
    }
    __nv_bfloat16 hi = __float2bfloat16_rn(w);
    float lo = w - __bfloat162float(hi);
    *reinterpret_cast<__nv_bfloat16*>(g_Whi + dst) = hi;
    *reinterpret_cast<__nv_bfloat16*>(g_Wlo + dst) = __float2bfloat16_rn(lo);
}

// ---------------- convert x -> A tiles (hi/lo, ldmatrix layout) ----------------
__global__ void k_convert_x(const float* __restrict__ x) {
    int gwarp = (blockIdx.x * blockDim.x + threadIdx.x) >> 5;
    int lane  = threadIdx.x & 31;
    if (gwarp >= NNODES) return;
    float4 v = *reinterpret_cast<const float4*>(x + (size_t)gwarp * HID + lane * 4);
    int tile = gwarp >> 7, r = gwarp & 127;
    uint32_t off = tile_off(r, lane * 4);
    split_store((char*)g_Ahi + (size_t)tile * 32768,
                (char*)g_Alo + (size_t)tile * 32768, off, v);
}

// ---------------- tensor-core GEMM via mma.sync, split-bf16 x3 passes ----------
// C[M, NCOLS] = A[M,128] @ W[128,NCOLS]; 256 threads, warp tile 32 x NCOLS/2.
template <int NCOLS>
__global__ __launch_bounds__(256, 1)
void k_gemm_mma(const uint4* __restrict__ Bhi4, const uint4* __restrict__ Blo4,
                const float* __restrict__ bias, float* __restrict__ C) {
    constexpr int A_BYTES = 32768;                 // 128 rows x 256B
    constexpr int B_BYTES = NCOLS * 256;           // NCOLS rows x 256B
    constexpr int OFF_AHI = 0;
    constexpr int OFF_ALO = A_BYTES;
    constexpr int OFF_BHI = 2 * A_BYTES;
    constexpr int OFF_BLO = 2 * A_BYTES + B_BYTES;
    constexpr int NT8 = NCOLS / 16;                // n-tiles (of 8) per warp
    extern __shared__ __align__(16) char smem[];

    const int tid  = threadIdx.x;
    const int wid  = tid >> 5;
    const int lane = tid & 31;
    const int tile = blockIdx.x;

    // identity copies (gmem already in ldmatrix tile layout)
    {
        const uint4* srcH = reinterpret_cast<const uint4*>((const char*)g_Ahi + (size_t)tile * A_BYTES);
        const uint4* srcL = reinterpret_cast<const uint4*>((const char*)g_Alo + (size_t)tile * A_BYTES);
        uint4* dH = reinterpret_cast<uint4*>(smem + OFF_AHI);
        uint4* dL = reinterpret_cast<uint4*>(smem + OFF_ALO);
        #pragma unroll
        for (int i = tid; i < A_BYTES / 16; i += 256) { dH[i] = srcH[i]; dL[i] = srcL[i]; }
        uint4* bH = reinterpret_cast<uint4*>(smem + OFF_BHI);
        uint4* bL = reinterpret_cast<uint4*>(smem + OFF_BLO);
        #pragma unroll
        for (int i = tid; i < B_BYTES / 16; i += 256) { bH[i] = Bhi4[i]; bL[i] = Blo4[i]; }
    }
    __syncthreads();

    const int wm  = wid >> 1;                 // 0..3
    const int wn  = wid & 1;                  // 0..1
    const int m0w = wm * 32;
    const int n0w = wn * (NCOLS / 2);

    float acc[2][NT8][4];
    #pragma unroll
    for (int mi = 0; mi < 2; mi++)
        #pragma unroll
        for (int ni = 0; ni < NT8; ni++)
            #pragma unroll
            for (int q = 0; q < 4; q++) acc[mi][ni][q] = 0.0f;

    const uint32_t sb = smem_to_u32(smem);
    const int arow    = m0w + (lane & 15);
    const int asw     = arow & 7;
    const int akc_add = lane >> 4;
    const int bn      = n0w + (lane & 7) + ((lane >> 4) << 3);
    const int bsw     = bn & 7;
    const int bkc_add = (lane >> 3) & 1;

    #pragma unroll
    for (int pass = 0; pass < 3; pass++) {
        const uint32_t Ab = sb + ((pass == 2) ? OFF_ALO : OFF_AHI);
        const uint32_t Bb = sb + ((pass == 1) ? OFF_BLO : OFF_BHI);
        #pragma unroll
        for (int s = 0; s < 8; s++) {
            const int kca = 2 * s + akc_add;
            const int kcb = 2 * s + bkc_add;
            uint32_t a[2][4];
            #pragma unroll
            for (int mi = 0; mi < 2; mi++)
                ldsm4(a[mi], Ab + (uint32_t)((arow + mi * 16) * 256 + 16 * (kca ^ asw)));
            uint32_t b[NT8][2];
            #pragma unroll
            for (int nj = 0; nj < NT8 / 2; nj++) {
                uint32_t r[4];
                ldsm4(r, Bb + (uint32_t)((bn + nj * 16) * 256 + 16 * (kcb ^ bsw)));
                b[2 * nj][0] = r[0]; b[2 * nj][1] = r[1];
                b[2 * nj + 1][0] = r[2]; b[2 * nj + 1][1] = r[3];
            }
            #pragma unroll
            for (int mi = 0; mi < 2; mi++)
                #pragma unroll
                for (int ni = 0; ni < NT8; ni++)
                    mma16816(acc[mi][ni], a[mi], b[ni]);
        }
    }

    // epilogue: fragment c: lane l -> rows (l>>2), (l>>2)+8; cols (l&3)*2, +1
    const int rbase = tile * 128 + m0w;
    #pragma unroll
    for (int mi = 0; mi < 2; mi++) {
        int r0 = rbase + mi * 16 + (lane >> 2);
        int r1 = r0 + 8;
        #pragma unroll
        for (int ni = 0; ni < NT8; ni++) {
            int c = n0w + ni * 8 + (lane & 3) * 2;
            float bx = 0.f, by = 0.f;
            if (bias) { bx = bias[c]; by = bias[c + 1]; }
            if (r0 < NNODES) {
                float2 v = make_float2(acc[mi][ni][0] + bx, acc[mi][ni][1] + by);
                *reinterpret_cast<float2*>(C + (size_t)r0 * NCOLS + c) = v;
            }
            if (r1 < NNODES) {
                float2 v = make_float2(acc[mi][ni][2] + bx, acc[mi][ni][3] + by);
                *reinterpret_cast<float2*>(C + (size_t)r1 * NCOLS + c) = v;
            }
        }
    }
}

// ---------------- aggregation (4-way edge ILP): gather fp32 h, norms+bias+relu,
//                  emit split A tiles ----------------
__global__ void k_agg(const float* __restrict__ h,
                      const float* __restrict__ bias) {
    int gwarp = (blockIdx.x * blockDim.x + threadIdx.x) >> 5;
    int lane  = threadIdx.x & 31;
    if (gwarp >= NNODES) return;
    const int n = gwarp;

    const float dn = g_dinv[n];
    const size_t feat = (size_t)lane * 4;

    float4 self = *reinterpret_cast<const float4*>(h + (size_t)n * HID + feat);
    const float sn = dn * dn;
    float4 acc0 = make_float4(self.x * sn, self.y * sn, self.z * sn, self.w * sn);
    float4 acc1 = make_float4(0.f, 0.f, 0.f, 0.f);
    float4 acc2 = make_float4(0.f, 0.f, 0.f, 0.f);
    float4 acc3 = make_float4(0.f, 0.f, 0.f, 0.f);

    const int beg = g_rowptr[n];
    const int end = g_rowptr[n + 1];

    int e = beg;
    // 4-edge batches: 4 independent gathers in flight per lane
    for (; e + 4 <= end; e += 4) {
        int   r0 = g_srow[e],     r1 = g_srow[e + 1];
        int   r2 = g_srow[e + 2], r3 = g_srow[e + 3];
        float w0 = g_sdinv[e] * dn,     w1 = g_sdinv[e + 1] * dn;
        float w2 = g_sdinv[e + 2] * dn, w3 = g_sdinv[e + 3] * dn;
        float4 v0 = *reinterpret_cast<const float4*>(h + (size_t)r0 * HID + feat);
        float4 v1 = *reinterpret_cast<const float4*>(h + (size_t)r1 * HID + feat);
        float4 v2 = *reinterpret_cast<const float4*>(h + (size_t)r2 * HID + feat);
        float4 v3 = *reinterpret_cast<const float4*>(h + (size_t)r3 * HID + feat);
        acc0.x += v0.x * w0; acc0.y += v0.y * w0; acc0.z += v0.z * w0; acc0.w += v0.w * w0;
        acc1.x += v1.x * w1; acc1.y += v1.y * w1; acc1.z += v1.z * w1; acc1.w += v1.w * w1;
        acc2.x += v2.x * w2; acc2.y += v2.y * w2; acc2.z += v2.z * w2; acc2.w += v2.w * w2;
        acc3.x += v3.x * w3; acc3.y += v3.y * w3; acc3.z += v3.z * w3; acc3.w += v3.w * w3;
    }
    // tail
    for (; e < end; ++e) {
        int   r = g_srow[e];
        float w = g_sdinv[e] * dn;
        float4 v = *reinterpret_cast<const float4*>(h + (size_t)r * HID + feat);
        acc0.x += v.x * w; acc0.y += v.y * w; acc0.z += v.z * w; acc0.w += v.w * w;
    }

    float4 acc;
    acc.x = (acc0.x + acc1.x) + (acc2.x + acc3.x);
    acc.y = (acc0.y + acc1.y) + (acc2.y + acc3.y);
    acc.z = (acc0.z + acc1.z) + (acc2.z + acc3.z);
    acc.w = (acc0.w + acc1.w) + (acc2.w + acc3.w);

    float4 b = *reinterpret_cast<const float4*>(bias + feat);
    acc.x = fmaxf(acc.x + b.x, 0.0f);
    acc.y = fmaxf(acc.y + b.y, 0.0f);
    acc.z = fmaxf(acc.z + b.z, 0.0f);
    acc.w = fmaxf(acc.w + b.w, 0.0f);

    int tile = n >> 7, r = n & 127;
    uint32_t off = tile_off(r, lane * 4);
    split_store((char*)g_Ahi + (size_t)tile * 32768,
                (char*)g_Alo + (size_t)tile * 32768, off, acc);
}

// ---------------- launch ----------------
extern "C" void kernel_launch(void* const* d_in, const int* in_sizes, int n_in,
                              void* d_out, int out_size) {
    const float* x    = (const float*)d_in[0];
    const int*   ei   = (const int*)d_in[1];
    const int*   row  = ei;
    const int*   col  = ei + NEDGES;
    const float* W0   = (const float*)d_in[2];
    const float* b0   = (const float*)d_in[3];
    const float* W1   = (const float*)d_in[4];
    const float* b1   = (const float*)d_in[5];
    const float* W2   = (const float*)d_in[6];
    const float* b2   = (const float*)d_in[7];
    const float* Wlin = (const float*)d_in[8];
    const float* blin = (const float*)d_in[9];
    float* out = (float*)d_out;

    float* hPtr;   cudaGetSymbolAddress((void**)&hPtr, g_h);
    int*   cntPtr; cudaGetSymbolAddress((void**)&cntPtr, g_cnt);
    unsigned char *whi, *wlo;
    cudaGetSymbolAddress((void**)&whi, g_Whi);
    cudaGetSymbolAddress((void**)&wlo, g_Wlo);

    constexpr int SMEM_128 = 2 * 32768 + 2 * 32768;  // 131072
    constexpr int SMEM_64  = 2 * 32768 + 2 * 16384;  //  98304
    cudaFuncSetAttribute(k_gemm_mma<128>, cudaFuncAttributeMaxDynamicSharedMemorySize, SMEM_128);
    cudaFuncSetAttribute(k_gemm_mma<64>,  cudaFuncAttributeMaxDynamicSharedMemorySize, SMEM_64);

    // preprocessing
    cudaMemsetAsync(cntPtr, 0, NNODES * sizeof(int));
    k_count<<<(NEDGES + 255) / 256, 256>>>(col);
    k_sum_dinv<<<NSCANBLK, SCAN_BLK>>>();
    k_scan_bsum<<<1, 64>>>();
    k_scan_apply<<<NSCANBLK, SCAN_BLK>>>();
    k_scatter<<<(NEDGES + 255) / 256, 256>>>(row, col);
    k_wprep<<<(3 * 16384 + 8192 + 255) / 256, 256>>>(W0, W1, W2, Wlin);
    k_convert_x<<<(NNODES * 32 + 255) / 256, 256>>>(x);

    const int agg_blocks = (NNODES * 32 + 255) / 256;

    // layer 0
    k_gemm_mma<128><<<NT, 256, SMEM_128>>>((const uint4*)(whi + 0 * 32768),
                                           (const uint4*)(wlo + 0 * 32768), nullptr, hPtr);
    k_agg<<<agg_blocks, 256>>>(hPtr, b0);
    // layer 1
    k_gemm_mma<128><<<NT, 256, SMEM_128>>>((const uint4*)(whi + 1 * 32768),
                                           (const uint4*)(wlo + 1 * 32768), nullptr, hPtr);
    k_agg<<<agg_blocks, 256>>>(hPtr, b1);
    // layer 2
    k_gemm_mma<128><<<NT, 256, SMEM_128>>>((const uint4*)(whi + 2 * 32768),
                                           (const uint4*)(wlo + 2 * 32768), nullptr, hPtr);
    k_agg<<<agg_blocks, 256>>>(hPtr, b2);
    // head
    k_gemm_mma<64><<<NT, 256, SMEM_64>>>((const uint4*)(whi + 3 * 32768),
                                         (const uint4*)(wlo + 3 * 32768), blin, out);
}

// round 7
// speedup vs baseline: 2.3300x; 1.0307x over previous
#include <cuda_runtime.h>
#include <cuda_bf16.h>
#include <cstdint>

#define NNODES 50000
#define NEDGES 640000
#define HID    128
#define CLS    64
#define NT     391            // ceil(50000/128) M-tiles

#define SCAN_BLK 1024
#define NSCANBLK ((NNODES + SCAN_BLK - 1) / SCAN_BLK)   // 49

typedef unsigned long long u64;

// ---------------- scratch (static __device__, no allocation) ----------------
__device__ float g_h[NNODES * HID];                        // fp32 hidden (ping)
__device__ float g_h2[NNODES * HID];                       // fp32 hidden (pong)
__device__ __align__(16) unsigned char g_Whi[3 * 32768 + 16384]; // W^T tiles
__device__ __align__(16) unsigned char g_Wlo[3 * 32768 + 16384];
__device__ float g_dinv[NNODES];
__device__ int   g_cnt[NNODES];      // zero-initialized; invariant: zero at launch start
__device__ int   g_rowptr[NNODES + 1];
__device__ int   g_pos[NNODES];
__device__ int   g_bsum[NSCANBLK];
__device__ int   g_srow[NEDGES];
__device__ float g_sdinv[NEDGES];

// ---------------- helpers ----------------
__device__ __forceinline__ uint32_t smem_to_u32(const void* p) {
    uint32_t a;
    asm("{ .reg .u64 t; cvta.to.shared.u64 t, %1; cvt.u32.u64 %0, t; }" : "=r"(a) : "l"(p));
    return a;
}

// tile layout: 128-bf16 rows (256B), 16B chunks XOR-swizzled by row for
// conflict-free ldmatrix. byte(r, k) = r*256 + 16*((k>>3) ^ (r&7)) + (k&7)*2
__device__ __forceinline__ uint32_t tile_off(int r, int k) {
    return (uint32_t)(r * 256 + 16 * (((k >> 3) ^ (r & 7))) + (k & 7) * 2);
}

__device__ __forceinline__ void ldsm4(uint32_t* r, uint32_t addr) {
    asm volatile("ldmatrix.sync.aligned.m8n8.x4.shared.b16 {%0,%1,%2,%3}, [%4];"
                 : "=r"(r[0]), "=r"(r[1]), "=r"(r[2]), "=r"(r[3]) : "r"(addr));
}
__device__ __forceinline__ void mma16816(float* c, const uint32_t* a, const uint32_t* b) {
    asm volatile("mma.sync.aligned.m16n8k16.row.col.f32.bf16.bf16.f32 "
                 "{%0,%1,%2,%3}, {%4,%5,%6,%7}, {%8,%9}, {%0,%1,%2,%3};"
                 : "+f"(c[0]), "+f"(c[1]), "+f"(c[2]), "+f"(c[3])
                 : "r"(a[0]), "r"(a[1]), "r"(a[2]), "r"(a[3]), "r"(b[0]), "r"(b[1]));
}

// split one float4 into hi/lo bf16x4 and store 8B each
__device__ __forceinline__ void split_store(char* hiB, char* loB, uint32_t off, float4 v) {
    __nv_bfloat162 h0 = __floats2bfloat162_rn(v.x, v.y);
    __nv_bfloat162 h1 = __floats2bfloat162_rn(v.z, v.w);
    float rx = v.x - __low2float(h0);
    float ry = v.y - __high2float(h0);
    float rz = v.z - __low2float(h1);
    float rw = v.w - __high2float(h1);
    __nv_bfloat162 l0 = __floats2bfloat162_rn(rx, ry);
    __nv_bfloat162 l1 = __floats2bfloat162_rn(rz, rw);
    uint2 hu = make_uint2(*(uint32_t*)&h0, *(uint32_t*)&h1);
    uint2 lu = make_uint2(*(uint32_t*)&l0, *(uint32_t*)&l1);
    *reinterpret_cast<uint2*>(hiB + off) = hu;
    *reinterpret_cast<uint2*>(loB + off) = lu;
}

// ---------------- preprocessing ----------------
__global__ void k_count(const int* __restrict__ col) {
    int e = blockIdx.x * blockDim.x + threadIdx.x;
    if (e < NEDGES) atomicAdd(&g_cnt[col[e]], 1);
}

// per-block sum of cnt + dinv computation
__global__ void k_sum_dinv() {
    __shared__ int warp_sums[32];
    const int tid  = threadIdx.x;
    const int lane = tid & 31;
    const int wid  = tid >> 5;
    int i = blockIdx.x * SCAN_BLK + tid;
    int c = (i < NNODES) ? g_cnt[i] : 0;
    if (i < NNODES) g_dinv[i] = rsqrtf((float)c + 1.0f);
    int x = c;
    #pragma unroll
    for (int o = 16; o > 0; o >>= 1) x += __shfl_down_sync(0xffffffffu, x, o);
    if (lane == 0) warp_sums[wid] = x;
    __syncthreads();
    if (wid == 0) {
        int s = warp_sums[lane];
        #pragma unroll
        for (int o = 16; o > 0; o >>= 1) s += __shfl_down_sync(0xffffffffu, s, o);
        if (lane == 0) g_bsum[blockIdx.x] = s;
    }
}

// per-block scan + inline block-prefix of g_bsum -> rowptr/pos; clears g_cnt
__global__ void k_scan_apply() {
    __shared__ int warp_sums[32];
    __shared__ int s_base;
    const int tid  = threadIdx.x;
    const int lane = tid & 31;
    const int wid  = tid >> 5;
    const int bid  = blockIdx.x;

    // warp 0: exclusive prefix of block sums for this block
    if (wid == 0) {
        int v = ((lane      < bid) ? g_bsum[lane]      : 0)
              + ((lane + 32 < bid) ? g_bsum[lane + 32] : 0);
        #pragma unroll
        for (int o = 16; o > 0; o >>= 1) v += __shfl_down_sync(0xffffffffu, v, o);
        if (lane == 0) s_base = v;
    }
    if (bid == 0 && tid == 0) g_rowptr[NNODES] = NEDGES;

    int i = bid * SCAN_BLK + tid;
    int v = 0;
    if (i < NNODES) { v = g_cnt[i]; g_cnt[i] = 0; }   // read + restore invariant

    int x = v;
    #pragma unroll
    for (int o = 1; o < 32; o <<= 1) {
        int y = __shfl_up_sync(0xffffffffu, x, o);
        if (lane >= o) x += y;
    }
    if (lane == 31) warp_sums[wid] = x;
    __syncthreads();
    if (wid == 0) {
        int s = warp_sums[lane];
        #pragma unroll
        for (int o = 1; o < 32; o <<= 1) {
            int y = __shfl_up_sync(0xffffffffu, s, o);
            if (lane >= o) s += y;
        }
        warp_sums[lane] = s;
    }
    __syncthreads();
    int excl = s_base + x - v + (wid > 0 ? warp_sums[wid - 1] : 0);
    if (i < NNODES) { g_rowptr[i] = excl; g_pos[i] = excl; }
}

__global__ void k_scatter(const int* __restrict__ row, const int* __restrict__ col) {
    int e = blockIdx.x * blockDim.x + threadIdx.x;
    if (e < NEDGES) {
        int c = col[e];
        int r = row[e];
        int p = atomicAdd(&g_pos[c], 1);
        g_srow[p]  = r;
        g_sdinv[p] = g_dinv[r];
    }
}

// ---------------- weight prep: W[K,N] -> W^T[N,K] tiles, hi/lo ----------------
__global__ void k_wprep(const float* __restrict__ W0, const float* __restrict__ W1,
                        const float* __restrict__ W2, const float* __restrict__ Wlin) {
    int idx = blockIdx.x * blockDim.x + threadIdx.x;   // 0 .. 57343
    if (idx >= 3 * 16384 + 8192) return;
    float w;
    uint32_t dst;
    if (idx < 3 * 16384) {
        int g = idx >> 14;
        int rem = idx & 16383;
        int k = rem >> 7;
        int n = rem & 127;
        const float* W = (g == 0) ? W0 : (g == 1) ? W1 : W2;
        w = W[k * 128 + n];
        dst = g * 32768 + tile_off(n, k);
    } else {
        int rem = idx - 3 * 16384;     // 0..8191
        int k = rem >> 6;
        int n = rem & 63;
        w = Wlin[k * 64 + n];
        dst = 3 * 32768 + tile_off(n, k);
    }
    __nv_bfloat16 hi = __float2bfloat16_rn(w);
    float lo = w - __bfloat162float(hi);
    *reinterpret_cast<__nv_bfloat16*>(g_Whi + dst) = hi;
    *reinterpret_cast<__nv_bfloat16*>(g_Wlo + dst) = __float2bfloat16_rn(lo);
}

// ---------------- tensor-core GEMM via mma.sync, split-bf16 x3 passes ----------
// C[M, NCOLS] = A[M,128] @ W[128,NCOLS]; A fp32, split hi/lo into smem on load.
// 256 threads, warp tile 32 x NCOLS/2.
template <int NCOLS>
__global__ __launch_bounds__(256, 1)
void k_gemm_mma(const float* __restrict__ A,
                const uint4* __restrict__ Bhi4, const uint4* __restrict__ Blo4,
                const float* __restrict__ bias, float* __restrict__ C) {
    constexpr int A_BYTES = 32768;                 // 128 rows x 256B
    constexpr int B_BYTES = NCOLS * 256;           // NCOLS rows x 256B
    constexpr int OFF_AHI = 0;
    constexpr int OFF_ALO = A_BYTES;
    constexpr int OFF_BHI = 2 * A_BYTES;
    constexpr int OFF_BLO = 2 * A_BYTES + B_BYTES;
    constexpr int NT8 = NCOLS / 16;                // n-tiles (of 8) per warp
    extern __shared__ __align__(16) char smem[];

    const int tid  = threadIdx.x;
    const int wid  = tid >> 5;
    const int lane = tid & 31;
    const int tile = blockIdx.x;

    // A: load fp32, split hi/lo into ldmatrix-layout smem tiles
    {
        char* hiB = smem + OFF_AHI;
        char* loB = smem + OFF_ALO;
        #pragma unroll
        for (int it = 0; it < 16; it++) {
            int idx = tid + it * 256;          // 0..4095 float4 ids
            int r   = idx >> 5;                // 0..127
            int c4  = (idx & 31) * 4;          // 0..124
            int gr  = tile * 128 + r;
            float4 v = make_float4(0.f, 0.f, 0.f, 0.f);
            if (gr < NNODES)
                v = *reinterpret_cast<const float4*>(A + (size_t)gr * HID + c4);
            split_store(hiB, loB, tile_off(r, c4), v);
        }
        // B: identity copy (pre-split, pre-swizzled)
        uint4* bH = reinterpret_cast<uint4*>(smem + OFF_BHI);
        uint4* bL = reinterpret_cast<uint4*>(smem + OFF_BLO);
        #pragma unroll
        for (int i = tid; i < B_BYTES / 16; i += 256) { bH[i] = Bhi4[i]; bL[i] = Blo4[i]; }
    }
    __syncthreads();

    const int wm  = wid >> 1;                 // 0..3
    const int wn  = wid & 1;                  // 0..1
    const int m0w = wm * 32;
    const int n0w = wn * (NCOLS / 2);

    float acc[2][NT8][4];
    #pragma unroll
    for (int mi = 0; mi < 2; mi++)
        #pragma unroll
        for (int ni = 0; ni < NT8; ni++)
            #pragma unroll
            for (int q = 0; q < 4; q++) acc[mi][ni][q] = 0.0f;

    const uint32_t sb = smem_to_u32(smem);
    const int arow    = m0w + (lane & 15);
    const int asw     = arow & 7;
    const int akc_add = lane >> 4;
    const int bn      = n0w + (lane & 7) + ((lane >> 4) << 3);
    const int bsw     = bn & 7;
    const int bkc_add = (lane >> 3) & 1;

    #pragma unroll
    for (int pass = 0; pass < 3; pass++) {
        const uint32_t Ab = sb + ((pass == 2) ? OFF_ALO : OFF_AHI);
        const uint32_t Bb = sb + ((pass == 1) ? OFF_BLO : OFF_BHI);
        #pragma unroll
        for (int s = 0; s < 8; s++) {
            const int kca = 2 * s + akc_add;
            const int kcb = 2 * s + bkc_add;
            uint32_t a[2][4];
            #pragma unroll
            for (int mi = 0; mi < 2; mi++)
                ldsm4(a[mi], Ab + (uint32_t)((arow + mi * 16) * 256 + 16 * (kca ^ asw)));
            uint32_t b[NT8][2];
            #pragma unroll
            for (int nj = 0; nj < NT8 / 2; nj++) {
                uint32_t r[4];
                ldsm4(r, Bb + (uint32_t)((bn + nj * 16) * 256 + 16 * (kcb ^ bsw)));
                b[2 * nj][0] = r[0]; b[2 * nj][1] = r[1];
                b[2 * nj + 1][0] = r[2]; b[2 * nj + 1][1] = r[3];
            }
            #pragma unroll
            for (int mi = 0; mi < 2; mi++)
                #pragma unroll
                for (int ni = 0; ni < NT8; ni++)
                    mma16816(acc[mi][ni], a[mi], b[ni]);
        }
    }

    // epilogue: fragment c: lane l -> rows (l>>2), (l>>2)+8; cols (l&3)*2, +1
    const int rbase = tile * 128 + m0w;
    #pragma unroll
    for (int mi = 0; mi < 2; mi++) {
        int r0 = rbase + mi * 16 + (lane >> 2);
        int r1 = r0 + 8;
        #pragma unroll
        for (int ni = 0; ni < NT8; ni++) {
            int c = n0w + ni * 8 + (lane & 3) * 2;
            float bx = 0.f, by = 0.f;
            if (bias) { bx = bias[c]; by = bias[c + 1]; }
            if (r0 < NNODES) {
                float2 v = make_float2(acc[mi][ni][0] + bx, acc[mi][ni][1] + by);
                *reinterpret_cast<float2*>(C + (size_t)r0 * NCOLS + c) = v;
            }
            if (r1 < NNODES) {
                float2 v = make_float2(acc[mi][ni][2] + bx, acc[mi][ni][3] + by);
                *reinterpret_cast<float2*>(C + (size_t)r1 * NCOLS + c) = v;
            }
        }
    }
}

// ---------------- aggregation (4-way edge ILP): fp32 in, fp32 out ----------------
__global__ void k_agg(const float* __restrict__ h,
                      const float* __restrict__ bias,
                      float* __restrict__ out) {
    int gwarp = (blockIdx.x * blockDim.x + threadIdx.x) >> 5;
    int lane  = threadIdx.x & 31;
    if (gwarp >= NNODES) return;
    const int n = gwarp;

    const float dn = g_dinv[n];
    const size_t feat = (size_t)lane * 4;

    float4 self = *reinterpret_cast<const float4*>(h + (size_t)n * HID + feat);
    const float sn = dn * dn;
    float4 acc0 = make_float4(self.x * sn, self.y * sn, self.z * sn, self.w * sn);
    float4 acc1 = make_float4(0.f, 0.f, 0.f, 0.f);
    float4 acc2 = make_float4(0.f, 0.f, 0.f, 0.f);
    float4 acc3 = make_float4(0.f, 0.f, 0.f, 0.f);

    const int beg = g_rowptr[n];
    const int end = g_rowptr[n + 1];

    int e = beg;
    for (; e + 4 <= end; e += 4) {
        int   r0 = g_srow[e],     r1 = g_srow[e + 1];
        int   r2 = g_srow[e + 2], r3 = g_srow[e + 3];
        float w0 = g_sdinv[e] * dn,     w1 = g_sdinv[e + 1] * dn;
        float w2 = g_sdinv[e + 2] * dn, w3 = g_sdinv[e + 3] * dn;
        float4 v0 = *reinterpret_cast<const float4*>(h + (size_t)r0 * HID + feat);
        float4 v1 = *reinterpret_cast<const float4*>(h + (size_t)r1 * HID + feat);
        float4 v2 = *reinterpret_cast<const float4*>(h + (size_t)r2 * HID + feat);
        float4 v3 = *reinterpret_cast<const float4*>(h + (size_t)r3 * HID + feat);
        acc0.x += v0.x * w0; acc0.y += v0.y * w0; acc0.z += v0.z * w0; acc0.w += v0.w * w0;
        acc1.x += v1.x * w1; acc1.y += v1.y * w1; acc1.z += v1.z * w1; acc1.w += v1.w * w1;
        acc2.x += v2.x * w2; acc2.y += v2.y * w2; acc2.z += v2.z * w2; acc2.w += v2.w * w2;
        acc3.x += v3.x * w3; acc3.y += v3.y * w3; acc3.z += v3.z * w3; acc3.w += v3.w * w3;
    }
    for (; e < end; ++e) {
        int   r = g_srow[e];
        float w = g_sdinv[e] * dn;
        float4 v = *reinterpret_cast<const float4*>(h + (size_t)r * HID + feat);
        acc0.x += v.x * w; acc0.y += v.y * w; acc0.z += v.z * w; acc0.w += v.w * w;
    }

    float4 acc;
    acc.x = (acc0.x + acc1.x) + (acc2.x + acc3.x);
    acc.y = (acc0.y + acc1.y) + (acc2.y + acc3.y);
    acc.z = (acc0.z + acc1.z) + (acc2.z + acc3.z);
    acc.w = (acc0.w + acc1.w) + (acc2.w + acc3.w);

    float4 b = *reinterpret_cast<const float4*>(bias + feat);
    acc.x = fmaxf(acc.x + b.x, 0.0f);
    acc.y = fmaxf(acc.y + b.y, 0.0f);
    acc.z = fmaxf(acc.z + b.z, 0.0f);
    acc.w = fmaxf(acc.w + b.w, 0.0f);

    *reinterpret_cast<float4*>(out + (size_t)n * HID + feat) = acc;
}

// ---------------- launch ----------------
extern "C" void kernel_launch(void* const* d_in, const int* in_sizes, int n_in,
                              void* d_out, int out_size) {
    const float* x    = (const float*)d_in[0];
    const int*   ei   = (const int*)d_in[1];
    const int*   row  = ei;
    const int*   col  = ei + NEDGES;
    const float* W0   = (const float*)d_in[2];
    const float* b0   = (const float*)d_in[3];
    const float* W1   = (const float*)d_in[4];
    const float* b1   = (const float*)d_in[5];
    const float* W2   = (const float*)d_in[6];
    const float* b2   = (const float*)d_in[7];
    const float* Wlin = (const float*)d_in[8];
    const float* blin = (const float*)d_in[9];
    float* out = (float*)d_out;

    float *hPtr, *h2Ptr;
    cudaGetSymbolAddress((void**)&hPtr, g_h);
    cudaGetSymbolAddress((void**)&h2Ptr, g_h2);
    unsigned char *whi, *wlo;
    cudaGetSymbolAddress((void**)&whi, g_Whi);
    cudaGetSymbolAddress((void**)&wlo, g_Wlo);

    constexpr int SMEM_128 = 2 * 32768 + 2 * 32768;  // 131072
    constexpr int SMEM_64  = 2 * 32768 + 2 * 16384;  //  98304
    cudaFuncSetAttribute(k_gemm_mma<128>, cudaFuncAttributeMaxDynamicSharedMemorySize, SMEM_128);
    cudaFuncSetAttribute(k_gemm_mma<64>,  cudaFuncAttributeMaxDynamicSharedMemorySize, SMEM_64);

    // preprocessing (g_cnt zero-invariant maintained by k_scan_apply)
    k_count<<<(NEDGES + 255) / 256, 256>>>(col);
    k_sum_dinv<<<NSCANBLK, SCAN_BLK>>>();
    k_scan_apply<<<NSCANBLK, SCAN_BLK>>>();
    k_scatter<<<(NEDGES + 255) / 256, 256>>>(row, col);
    k_wprep<<<(3 * 16384 + 8192 + 255) / 256, 256>>>(W0, W1, W2, Wlin);

    const int agg_blocks = (NNODES * 32 + 255) / 256;

    // layer 0
    k_gemm_mma<128><<<NT, 256, SMEM_128>>>(x, (const uint4*)(whi + 0 * 32768),
                                           (const uint4*)(wlo + 0 * 32768), nullptr, hPtr);
    k_agg<<<agg_blocks, 256>>>(hPtr, b0, h2Ptr);
    // layer 1
    k_gemm_mma<128><<<NT, 256, SMEM_128>>>(h2Ptr, (const uint4*)(whi + 1 * 32768),
                                           (const uint4*)(wlo + 1 * 32768), nullptr, hPtr);
    k_agg<<<agg_blocks, 256>>>(hPtr, b1, h2Ptr);
    // layer 2
    k_gemm_mma<128><<<NT, 256, SMEM_128>>>(h2Ptr, (const uint4*)(whi + 2 * 32768),
                                           (const uint4*)(wlo + 2 * 32768), nullptr, hPtr);
    k_agg<<<agg_blocks, 256>>>(hPtr, b2, h2Ptr);
    // head
    k_gemm_mma<64><<<NT, 256, SMEM_64>>>(h2Ptr, (const uint4*)(whi + 3 * 32768),
                                         (const uint4*)(wlo + 3 * 32768), blin, out);
}

// round 8
// speedup vs baseline: 2.4378x; 1.0463x over previous
#include <cuda_runtime.h>
#include <cuda_bf16.h>
#include <cstdint>

#define NNODES 50000
#define NEDGES 640000
#define HID    128
#define CLS    64
#define NT     391            // ceil(50000/128) M-tiles

#define SCAN_BLK 1024
#define NSCANBLK ((NNODES + SCAN_BLK - 1) / SCAN_BLK)   // 49

typedef unsigned long long u64;

// ---------------- scratch (static __device__, no allocation) ----------------
__device__ float g_h[NNODES * HID];                        // fp32 hidden (ping)
__device__ float g_h2[NNODES * HID];                       // fp32 hidden (pong)
__device__ __align__(16) unsigned char g_Whi[3 * 32768 + 16384]; // W^T tiles
__device__ __align__(16) unsigned char g_Wlo[3 * 32768 + 16384];
__device__ float g_dinv[NNODES];
__device__ int   g_cnt[NNODES];      // zero-initialized; invariant: zero at launch start
__device__ int   g_rowptr[NNODES + 1];
__device__ int   g_pos[NNODES];
__device__ int   g_bsum[NSCANBLK];
__device__ __align__(8) int2 g_edge[NEDGES];   // fused (srow, dinv-bits)

// ---------------- helpers ----------------
__device__ __forceinline__ uint32_t smem_to_u32(const void* p) {
    uint32_t a;
    asm("{ .reg .u64 t; cvta.to.shared.u64 t, %1; cvt.u32.u64 %0, t; }" : "=r"(a) : "l"(p));
    return a;
}

// tile layout: 128-bf16 rows (256B), 16B chunks XOR-swizzled by row for
// conflict-free ldmatrix. byte(r, k) = r*256 + 16*((k>>3) ^ (r&7)) + (k&7)*2
__device__ __forceinline__ uint32_t tile_off(int r, int k) {
    return (uint32_t)(r * 256 + 16 * (((k >> 3) ^ (r & 7))) + (k & 7) * 2);
}

__device__ __forceinline__ void ldsm4(uint32_t* r, uint32_t addr) {
    asm volatile("ldmatrix.sync.aligned.m8n8.x4.shared.b16 {%0,%1,%2,%3}, [%4];"
                 : "=r"(r[0]), "=r"(r[1]), "=r"(r[2]), "=r"(r[3]) : "r"(addr));
}
__device__ __forceinline__ void mma16816(float* c, const uint32_t* a, const uint32_t* b) {
    asm volatile("mma.sync.aligned.m16n8k16.row.col.f32.bf16.bf16.f32 "
                 "{%0,%1,%2,%3}, {%4,%5,%6,%7}, {%8,%9}, {%0,%1,%2,%3};"
                 : "+f"(c[0]), "+f"(c[1]), "+f"(c[2]), "+f"(c[3])
                 : "r"(a[0]), "r"(a[1]), "r"(a[2]), "r"(a[3]), "r"(b[0]), "r"(b[1]));
}

// split one float4 into hi/lo bf16x4 and store 8B each
__device__ __forceinline__ void split_store(char* hiB, char* loB, uint32_t off, float4 v) {
    __nv_bfloat162 h0 = __floats2bfloat162_rn(v.x, v.y);
    __nv_bfloat162 h1 = __floats2bfloat162_rn(v.z, v.w);
    float rx = v.x - __low2float(h0);
    float ry = v.y - __high2float(h0);
    float rz = v.z - __low2float(h1);
    float rw = v.w - __high2float(h1);
    __nv_bfloat162 l0 = __floats2bfloat162_rn(rx, ry);
    __nv_bfloat162 l1 = __floats2bfloat162_rn(rz, rw);
    uint2 hu = make_uint2(*(uint32_t*)&h0, *(uint32_t*)&h1);
    uint2 lu = make_uint2(*(uint32_t*)&l0, *(uint32_t*)&l1);
    *reinterpret_cast<uint2*>(hiB + off) = hu;
    *reinterpret_cast<uint2*>(loB + off) = lu;
}

// ---------------- preprocessing ----------------
__global__ void k_count(const int* __restrict__ col) {
    int e = blockIdx.x * blockDim.x + threadIdx.x;
    if (e < NEDGES) atomicAdd(&g_cnt[col[e]], 1);
}

// per-block sum of cnt + dinv computation
__global__ void k_sum_dinv() {
    __shared__ int warp_sums[32];
    const int tid  = threadIdx.x;
    const int lane = tid & 31;
    const int wid  = tid >> 5;
    int i = blockIdx.x * SCAN_BLK + tid;
    int c = (i < NNODES) ? g_cnt[i] : 0;
    if (i < NNODES) g_dinv[i] = rsqrtf((float)c + 1.0f);
    int x = c;
    #pragma unroll
    for (int o = 16; o > 0; o >>= 1) x += __shfl_down_sync(0xffffffffu, x, o);
    if (lane == 0) warp_sums[wid] = x;
    __syncthreads();
    if (wid == 0) {
        int s = warp_sums[lane];
        #pragma unroll
        for (int o = 16; o > 0; o >>= 1) s += __shfl_down_sync(0xffffffffu, s, o);
        if (lane == 0) g_bsum[blockIdx.x] = s;
    }
}

// per-block scan + inline block-prefix of g_bsum -> rowptr/pos; clears g_cnt
__global__ void k_scan_apply() {
    __shared__ int warp_sums[32];
    __shared__ int s_base;
    const int tid  = threadIdx.x;
    const int lane = tid & 31;
    const int wid  = tid >> 5;
    const int bid  = blockIdx.x;

    if (wid == 0) {
        int v = ((lane      < bid) ? g_bsum[lane]      : 0)
              + ((lane + 32 < bid) ? g_bsum[lane + 32] : 0);
        #pragma unroll
        for (int o = 16; o > 0; o >>= 1) v += __shfl_down_sync(0xffffffffu, v, o);
        if (lane == 0) s_base = v;
    }
    if (bid == 0 && tid == 0) g_rowptr[NNODES] = NEDGES;

    int i = bid * SCAN_BLK + tid;
    int v = 0;
    if (i < NNODES) { v = g_cnt[i]; g_cnt[i] = 0; }   // read + restore invariant

    int x = v;
    #pragma unroll
    for (int o = 1; o < 32; o <<= 1) {
        int y = __shfl_up_sync(0xffffffffu, x, o);
        if (lane >= o) x += y;
    }
    if (lane == 31) warp_sums[wid] = x;
    __syncthreads();
    if (wid == 0) {
        int s = warp_sums[lane];
        #pragma unroll
        for (int o = 1; o < 32; o <<= 1) {
            int y = __shfl_up_sync(0xffffffffu, s, o);
            if (lane >= o) s += y;
        }
        warp_sums[lane] = s;
    }
    __syncthreads();
    int excl = s_base + x - v + (wid > 0 ? warp_sums[wid - 1] : 0);
    if (i < NNODES) { g_rowptr[i] = excl; g_pos[i] = excl; }
}

__global__ void k_scatter(const int* __restrict__ row, const int* __restrict__ col) {
    int e = blockIdx.x * blockDim.x + threadIdx.x;
    if (e < NEDGES) {
        int c = col[e];
        int r = row[e];
        int p = atomicAdd(&g_pos[c], 1);
        g_edge[p] = make_int2(r, __float_as_int(g_dinv[r]));
    }
}

// ---------------- weight prep: W[K,N] -> W^T[N,K] tiles, hi/lo ----------------
__global__ void k_wprep(const float* __restrict__ W0, const float* __restrict__ W1,
                        const float* __restrict__ W2, const float* __restrict__ Wlin) {
    int idx = blockIdx.x * blockDim.x + threadIdx.x;   // 0 .. 57343
    if (idx >= 3 * 16384 + 8192) return;
    float w;
    uint32_t dst;
    if (idx < 3 * 16384) {
        int g = idx >> 14;
        int rem = idx & 16383;
        int k = rem >> 7;
        int n = rem & 127;
        const float* W = (g == 0) ? W0 : (g == 1) ? W1 : W2;
        w = W[k * 128 + n];
        dst = g * 32768 + tile_off(n, k);
    } else {
        int rem = idx - 3 * 16384;     // 0..8191
        int k = rem >> 6;
        int n = rem & 63;
        w = Wlin[k * 64 + n];
        dst = 3 * 32768 + tile_off(n, k);
    }
    __nv_bfloat16 hi = __float2bfloat16_rn(w);
    float lo = w - __bfloat162float(hi);
    *reinterpret_cast<__nv_bfloat16*>(g_Whi + dst) = hi;
    *reinterpret_cast<__nv_bfloat16*>(g_Wlo + dst) = __float2bfloat16_rn(lo);
}

// ---------------- tensor-core GEMM via mma.sync, split-bf16 x3 passes ----------
// C[M, NCOLS] = A[M,128] @ W[128,NCOLS]; A fp32, split hi/lo into smem on load.
// 256 threads, warp tile 32 x NCOLS/2.
template <int NCOLS>
__global__ __launch_bounds__(256, 1)
void k_gemm_mma(const float* __restrict__ A,
                const uint4* __restrict__ Bhi4, const uint4* __restrict__ Blo4,
                const float* __restrict__ bias, float* __restrict__ C) {
    constexpr int A_BYTES = 32768;                 // 128 rows x 256B
    constexpr int B_BYTES = NCOLS * 256;           // NCOLS rows x 256B
    constexpr int OFF_AHI = 0;
    constexpr int OFF_ALO = A_BYTES;
    constexpr int OFF_BHI = 2 * A_BYTES;
    constexpr int OFF_BLO = 2 * A_BYTES + B_BYTES;
    constexpr int NT8 = NCOLS / 16;                // n-tiles (of 8) per warp
    extern __shared__ __align__(16) char smem[];

    const int tid  = threadIdx.x;
    const int wid  = tid >> 5;
    const int lane = tid & 31;
    const int tile = blockIdx.x;

    // A: load fp32, split hi/lo into ldmatrix-layout smem tiles
    {
        char* hiB = smem + OFF_AHI;
        char* loB = smem + OFF_ALO;
        #pragma unroll
        for (int it = 0; it < 16; it++) {
            int idx = tid + it * 256;          // 0..4095 float4 ids
            int r   = idx >> 5;                // 0..127
            int c4  = (idx & 31) * 4;          // 0..124
            int gr  = tile * 128 + r;
            float4 v = make_float4(0.f, 0.f, 0.f, 0.f);
            if (gr < NNODES)
                v = *reinterpret_cast<const float4*>(A + (size_t)gr * HID + c4);
            split_store(hiB, loB, tile_off(r, c4), v);
        }
        // B: identity copy (pre-split, pre-swizzled)
        uint4* bH = reinterpret_cast<uint4*>(smem + OFF_BHI);
        uint4* bL = reinterpret_cast<uint4*>(smem + OFF_BLO);
        #pragma unroll
        for (int i = tid; i < B_BYTES / 16; i += 256) { bH[i] = Bhi4[i]; bL[i] = Blo4[i]; }
    }
    __syncthreads();

    const int wm  = wid >> 1;                 // 0..3
    const int wn  = wid & 1;                  // 0..1
    const int m0w = wm * 32;
    const int n0w = wn * (NCOLS / 2);

    float acc[2][NT8][4];
    #pragma unroll
    for (int mi = 0; mi < 2; mi++)
        #pragma unroll
        for (int ni = 0; ni < NT8; ni++)
            #pragma unroll
            for (int q = 0; q < 4; q++) acc[mi][ni][q] = 0.0f;

    const uint32_t sb = smem_to_u32(smem);
    const int arow    = m0w + (lane & 15);
    const int asw     = arow & 7;
    const int akc_add = lane >> 4;
    const int bn      = n0w + (lane & 7) + ((lane >> 4) << 3);
    const int bsw     = bn & 7;
    const int bkc_add = (lane >> 3) & 1;

    #pragma unroll
    for (int pass = 0; pass < 3; pass++) {
        const uint32_t Ab = sb + ((pass == 2) ? OFF_ALO : OFF_AHI);
        const uint32_t Bb = sb + ((pass == 1) ? OFF_BLO : OFF_BHI);
        #pragma unroll
        for (int s = 0; s < 8; s++) {
            const int kca = 2 * s + akc_add;
            const int kcb = 2 * s + bkc_add;
            uint32_t a[2][4];
            #pragma unroll
            for (int mi = 0; mi < 2; mi++)
                ldsm4(a[mi], Ab + (uint32_t)((arow + mi * 16) * 256 + 16 * (kca ^ asw)));
            uint32_t b[NT8][2];
            #pragma unroll
            for (int nj = 0; nj < NT8 / 2; nj++) {
                uint32_t r[4];
                ldsm4(r, Bb + (uint32_t)((bn + nj * 16) * 256 + 16 * (kcb ^ bsw)));
                b[2 * nj][0] = r[0]; b[2 * nj][1] = r[1];
                b[2 * nj + 1][0] = r[2]; b[2 * nj + 1][1] = r[3];
            }
            #pragma unroll
            for (int mi = 0; mi < 2; mi++)
                #pragma unroll
                for (int ni = 0; ni < NT8; ni++)
                    mma16816(acc[mi][ni], a[mi], b[ni]);
        }
    }

    // epilogue
    const int rbase = tile * 128 + m0w;
    #pragma unroll
    for (int mi = 0; mi < 2; mi++) {
        int r0 = rbase + mi * 16 + (lane >> 2);
        int r1 = r0 + 8;
        #pragma unroll
        for (int ni = 0; ni < NT8; ni++) {
            int c = n0w + ni * 8 + (lane & 3) * 2;
            float bx = 0.f, by = 0.f;
            if (bias) { bx = bias[c]; by = bias[c + 1]; }
            if (r0 < NNODES) {
                float2 v = make_float2(acc[mi][ni][0] + bx, acc[mi][ni][1] + by);
                *reinterpret_cast<float2*>(C + (size_t)r0 * NCOLS + c) = v;
            }
            if (r1 < NNODES) {
                float2 v = make_float2(acc[mi][ni][2] + bx, acc[mi][ni][3] + by);
                *reinterpret_cast<float2*>(C + (size_t)r1 * NCOLS + c) = v;
            }
        }
    }
}

// ---------------- aggregation (4-way edge ILP): fp32 in, fp32 out ----------------
__global__ void k_agg(const float* __restrict__ h,
                      const float* __restrict__ bias,
                      float* __restrict__ out) {
    int gwarp = (blockIdx.x * blockDim.x + threadIdx.x) >> 5;
    int lane  = threadIdx.x & 31;
    if (gwarp >= NNODES) return;
    const int n = gwarp;

    const float dn = g_dinv[n];
    const size_t feat = (size_t)lane * 4;

    float4 self = *reinterpret_cast<const float4*>(h + (size_t)n * HID + feat);
    const float sn = dn * dn;
    float4 acc0 = make_float4(self.x * sn, self.y * sn, self.z * sn, self.w * sn);
    float4 acc1 = make_float4(0.f, 0.f, 0.f, 0.f);
    float4 acc2 = make_float4(0.f, 0.f, 0.f, 0.f);
    float4 acc3 = make_float4(0.f, 0.f, 0.f, 0.f);

    const int beg = g_rowptr[n];
    const int end = g_rowptr[n + 1];

    int e = beg;
    for (; e + 4 <= end; e += 4) {
        int2 e0 = g_edge[e],     e1 = g_edge[e + 1];
        int2 e2 = g_edge[e + 2], e3 = g_edge[e + 3];
        float w0 = __int_as_float(e0.y) * dn, w1 = __int_as_float(e1.y) * dn;
        float w2 = __int_as_float(e2.y) * dn, w3 = __int_as_float(e3.y) * dn;
        float4 v0 = *reinterpret_cast<const float4*>(h + (size_t)e0.x * HID + feat);
        float4 v1 = *reinterpret_cast<const float4*>(h + (size_t)e1.x * HID + feat);
        float4 v2 = *reinterpret_cast<const float4*>(h + (size_t)e2.x * HID + feat);
        float4 v3 = *reinterpret_cast<const float4*>(h + (size_t)e3.x * HID + feat);
        acc0.x += v0.x * w0; acc0.y += v0.y * w0; acc0.z += v0.z * w0; acc0.w += v0.w * w0;
        acc1.x += v1.x * w1; acc1.y += v1.y * w1; acc1.z += v1.z * w1; acc1.w += v1.w * w1;
        acc2.x += v2.x * w2; acc2.y += v2.y * w2; acc2.z += v2.z * w2; acc2.w += v2.w * w2;
        acc3.x += v3.x * w3; acc3.y += v3.y * w3; acc3.z += v3.z * w3; acc3.w += v3.w * w3;
    }
    for (; e < end; ++e) {
        int2 ed = g_edge[e];
        float w = __int_as_float(ed.y) * dn;
        float4 v = *reinterpret_cast<const float4*>(h + (size_t)ed.x * HID + feat);
        acc0.x += v.x * w; acc0.y += v.y * w; acc0.z += v.z * w; acc0.w += v.w * w;
    }

    float4 acc;
    acc.x = (acc0.x + acc1.x) + (acc2.x + acc3.x);
    acc.y = (acc0.y + acc1.y) + (acc2.y + acc3.y);
    acc.z = (acc0.z + acc1.z) + (acc2.z + acc3.z);
    acc.w = (acc0.w + acc1.w) + (acc2.w + acc3.w);

    float4 b = *reinterpret_cast<const float4*>(bias + feat);
    acc.x = fmaxf(acc.x + b.x, 0.0f);
    acc.y = fmaxf(acc.y + b.y, 0.0f);
    acc.z = fmaxf(acc.z + b.z, 0.0f);
    acc.w = fmaxf(acc.w + b.w, 0.0f);

    *reinterpret_cast<float4*>(out + (size_t)n * HID + feat) = acc;
}

// ---------------- launch ----------------
extern "C" void kernel_launch(void* const* d_in, const int* in_sizes, int n_in,
                              void* d_out, int out_size) {
    const float* x    = (const float*)d_in[0];
    const int*   ei   = (const int*)d_in[1];
    const int*   row  = ei;
    const int*   col  = ei + NEDGES;
    const float* W0   = (const float*)d_in[2];
    const float* b0   = (const float*)d_in[3];
    const float* W1   = (const float*)d_in[4];
    const float* b1   = (const float*)d_in[5];
    const float* W2   = (const float*)d_in[6];
    const float* b2   = (const float*)d_in[7];
    const float* Wlin = (const float*)d_in[8];
    const float* blin = (const float*)d_in[9];
    float* out = (float*)d_out;

    float *hPtr, *h2Ptr;
    cudaGetSymbolAddress((void**)&hPtr, g_h);
    cudaGetSymbolAddress((void**)&h2Ptr, g_h2);
    unsigned char *whi, *wlo;
    cudaGetSymbolAddress((void**)&whi, g_Whi);
    cudaGetSymbolAddress((void**)&wlo, g_Wlo);

    constexpr int SMEM_128 = 2 * 32768 + 2 * 32768;  // 131072
    constexpr int SMEM_64  = 2 * 32768 + 2 * 16384;  //  98304
    cudaFuncSetAttribute(k_gemm_mma<128>, cudaFuncAttributeMaxDynamicSharedMemorySize, SMEM_128);
    cudaFuncSetAttribute(k_gemm_mma<64>,  cudaFuncAttributeMaxDynamicSharedMemorySize, SMEM_64);

    // one-time side-stream + events (handles only; no device memory)
    static cudaStream_t s2 = nullptr;
    static cudaEvent_t evFork = nullptr, evJoin = nullptr;
    if (s2 == nullptr) {
        cudaStreamCreateWithFlags(&s2, cudaStreamNonBlocking);
        cudaEventCreateWithFlags(&evFork, cudaEventDisableTiming);
        cudaEventCreateWithFlags(&evJoin, cudaEventDisableTiming);
    }

    // fork: weight prep + layer-0 GEMM (independent of graph) on s2
    cudaEventRecord(evFork, 0);
    cudaStreamWaitEvent(s2, evFork, 0);
    k_wprep<<<(3 * 16384 + 8192 + 255) / 256, 256, 0, s2>>>(W0, W1, W2, Wlin);
    k_gemm_mma<128><<<NT, 256, SMEM_128, s2>>>(x, (const uint4*)(whi + 0 * 32768),
                                               (const uint4*)(wlo + 0 * 32768), nullptr, hPtr);
    cudaEventRecord(evJoin, s2);

    // main stream: graph preprocessing (g_cnt zero-invariant kept by k_scan_apply)
    k_count<<<(NEDGES + 255) / 256, 256>>>(col);
    k_sum_dinv<<<NSCANBLK, SCAN_BLK>>>();
    k_scan_apply<<<NSCANBLK, SCAN_BLK>>>();
    k_scatter<<<(NEDGES + 255) / 256, 256>>>(row, col);

    // join
    cudaStreamWaitEvent(0, evJoin, 0);

    const int agg_blocks = (NNODES * 32 + 255) / 256;

    k_agg<<<agg_blocks, 256>>>(hPtr, b0, h2Ptr);
    // layer 1
    k_gemm_mma<128><<<NT, 256, SMEM_128>>>(h2Ptr, (const uint4*)(whi + 1 * 32768),
                                           (const uint4*)(wlo + 1 * 32768), nullptr, hPtr);
    k_agg<<<agg_blocks, 256>>>(hPtr, b1, h2Ptr);
    // layer 2
    k_gemm_mma<128><<<NT, 256, SMEM_128>>>(h2Ptr, (const uint4*)(whi + 2 * 32768),
                                           (const uint4*)(wlo + 2 * 32768), nullptr, hPtr);
    k_agg<<<agg_blocks, 256>>>(hPtr, b2, h2Ptr);
    // head
    k_gemm_mma<64><<<NT, 256, SMEM_64>>>(h2Ptr, (const uint4*)(whi + 3 * 32768),
                                         (const uint4*)(wlo + 3 * 32768), blin, out);
}